// round 1
// baseline (speedup 1.0000x reference)
#include <cuda_runtime.h>
#include <math.h>

#define N_ROWS 131072
#define DIM 64
#define K_EMB 1024

// Output layout (tuple order: quantized_st, quantized_original, perplexity, encodings)
#define OFF_QST   0
#define OFF_QORIG 8388608
#define OFF_PERP  16777216
#define OFF_ENC   16777217
#define ENC_COUNT ((size_t)N_ROWS * K_EMB)   // 134217728

__device__ int   g_idx[N_ROWS];
__device__ float g_b32[K_EMB];
__device__ int   g_counts[K_EMB];
__device__ int   g_flagged[N_ROWS];
__device__ int   g_nflag;

// ---------------------------------------------------------------------------
// Setup: per-embedding ||e||^2 (fp64 -> fp32), zero histogram + flag counter.
// ---------------------------------------------------------------------------
__global__ void vq_setup(const float* __restrict__ emb) {
    int k = blockIdx.x * blockDim.x + threadIdx.x;
    if (k == 0) g_nflag = 0;
    if (k < K_EMB) {
        const float* e = emb + (size_t)k * DIM;
        double s = 0.0;
        #pragma unroll
        for (int j = 0; j < DIM; j++) { double v = (double)e[j]; s += v * v; }
        g_b32[k] = (float)s;
        g_counts[k] = 0;
    }
}

// ---------------------------------------------------------------------------
// Main argmin: one thread per row. x row held in 64 registers, embedding
// streamed through smem in 128-row chunks. fp32 dot (4 independent chains),
// distance replicates ref rounding: d = fl(fl(a+b) - fl(2m)).
// Rows with top-2 margin <= 6 ulps are flagged for exact recompute.
// ---------------------------------------------------------------------------
__global__ __launch_bounds__(256, 2)
void vq_argmin(const float* __restrict__ xall, const float* __restrict__ emb) {
    __shared__ float4 es[128 * 16];   // 128 embeddings x 64 floats = 32 KB
    __shared__ float  bs[128];

    int row = blockIdx.x * 256 + threadIdx.x;

    float x[DIM];
    {
        const float4* xr = (const float4*)(xall + (size_t)row * DIM);
        #pragma unroll
        for (int i = 0; i < 16; i++) {
            float4 v = xr[i];
            x[4*i+0] = v.x; x[4*i+1] = v.y; x[4*i+2] = v.z; x[4*i+3] = v.w;
        }
    }
    // a32 = fp32(exact sum of squares); any integer-ulp difference vs the
    // reference's fp32 sum shifts all distances uniformly (uniform grid) and
    // cannot change the argmin.
    double ad = 0.0;
    #pragma unroll
    for (int j = 0; j < DIM; j++) ad += (double)x[j] * (double)x[j];
    float a32 = (float)ad;

    float d1 = 3.4e38f, d2 = 3.4e38f;
    int   i1 = 0;

    for (int kb = 0; kb < K_EMB; kb += 128) {
        __syncthreads();
        const float4* src = (const float4*)(emb + (size_t)kb * DIM);
        for (int t = threadIdx.x; t < 2048; t += 256) es[t] = src[t];
        if (threadIdx.x < 128) bs[threadIdx.x] = g_b32[kb + threadIdx.x];
        __syncthreads();

        #pragma unroll 2
        for (int kk = 0; kk < 128; kk++) {
            const float4* ev = es + kk * 16;
            float a0 = 0.f, a1 = 0.f, a2 = 0.f, a3 = 0.f;
            #pragma unroll
            for (int i = 0; i < 16; i++) {
                float4 e4 = ev[i];
                a0 = fmaf(x[4*i+0], e4.x, a0);
                a1 = fmaf(x[4*i+1], e4.y, a1);
                a2 = fmaf(x[4*i+2], e4.z, a2);
                a3 = fmaf(x[4*i+3], e4.w, a3);
            }
            float m  = __fadd_rn(__fadd_rn(a0, a1), __fadd_rn(a2, a3));
            float t  = __fadd_rn(a32, bs[kk]);          // fl(a+b)
            float d  = __fadd_rn(t, -__fmul_rn(2.0f, m)); // fl(t - 2m); 2m exact
            if (d < d1)      { d2 = d1; d1 = d; i1 = kb + kk; }
            else if (d < d2) { d2 = d; }
        }
    }
    g_idx[row] = i1;

    // Flag near-ties: margin within 6 ulps of |d1| (covers our fp32-dot noise
    // of <=1-2 grid steps plus the reference's own matmul rounding).
    float thr = 6.0f * fabsf(d1) * 1.1920929e-7f;
    if (!((d2 - d1) > thr)) {
        int p = atomicAdd(&g_nflag, 1);
        if (p < N_ROWS) g_flagged[p] = row;
    }
}

// ---------------------------------------------------------------------------
// Exact recompute of flagged rows: compensated Dot2 gives m32 = correctly
// rounded fp32 dot; same rounding chain; first-index tie-break.
// ---------------------------------------------------------------------------
__global__ void vq_exact(const float* __restrict__ xall, const float* __restrict__ emb) {
    __shared__ float xs[DIM];
    __shared__ float sd[256];
    __shared__ int   si[256];

    int nf = g_nflag;
    if (nf > N_ROWS) nf = N_ROWS;

    for (int f = blockIdx.x; f < nf; f += gridDim.x) {
        int row = g_flagged[f];
        __syncthreads();
        if (threadIdx.x < DIM) xs[threadIdx.x] = xall[(size_t)row * DIM + threadIdx.x];
        __syncthreads();

        double ad = 0.0;
        #pragma unroll
        for (int j = 0; j < DIM; j++) ad += (double)xs[j] * (double)xs[j];
        float a32 = (float)ad;

        float bestd = 3.4e38f;
        int   besti = 0x7fffffff;
        for (int k = threadIdx.x; k < K_EMB; k += 256) {
            const float* e = emb + (size_t)k * DIM;
            float s = 0.f, c = 0.f;
            #pragma unroll
            for (int j = 0; j < DIM; j++) {
                float xv = xs[j], ev = e[j];
                float p  = __fmul_rn(xv, ev);
                float pe = fmaf(xv, ev, -p);           // exact product error
                float t  = __fadd_rn(s, p);            // TwoSum (Knuth)
                float z  = __fadd_rn(t, -s);
                float se = __fadd_rn(__fadd_rn(s, -__fadd_rn(t, -z)),
                                     __fadd_rn(p, -z));
                s = t;
                c = __fadd_rn(c, __fadd_rn(pe, se));
            }
            float m = __fadd_rn(s, c);                 // ~correctly rounded dot
            float t2 = __fadd_rn(a32, g_b32[k]);
            float d  = __fadd_rn(t2, -__fmul_rn(2.0f, m));
            if (d < bestd || (d == bestd && k < besti)) { bestd = d; besti = k; }
        }
        sd[threadIdx.x] = bestd; si[threadIdx.x] = besti;
        __syncthreads();
        for (int off = 128; off > 0; off >>= 1) {
            if (threadIdx.x < off) {
                float od = sd[threadIdx.x + off];
                int   oi = si[threadIdx.x + off];
                if (od < sd[threadIdx.x] ||
                    (od == sd[threadIdx.x] && oi < si[threadIdx.x])) {
                    sd[threadIdx.x] = od; si[threadIdx.x] = oi;
                }
            }
            __syncthreads();
        }
        if (threadIdx.x == 0) g_idx[row] = si[0];
    }
}

// ---------------------------------------------------------------------------
// Zero the encodings region (misaligned start: 3 scalar head + float4 body
// + 1 scalar tail).
// ---------------------------------------------------------------------------
__global__ void vq_zero_enc(float* __restrict__ out) {
    float4* base = (float4*)(out + OFF_ENC + 3);       // element 16777220: 16B-aligned
    const size_t n4 = (ENC_COUNT - 3 - 1) / 4;         // 33554431 float4s
    size_t i      = (size_t)blockIdx.x * blockDim.x + threadIdx.x;
    size_t stride = (size_t)gridDim.x * blockDim.x;
    float4 z = make_float4(0.f, 0.f, 0.f, 0.f);
    for (; i < n4; i += stride) base[i] = z;
    if (blockIdx.x == 0 && threadIdx.x == 0) {
        out[OFF_ENC + 0] = 0.f;
        out[OFF_ENC + 1] = 0.f;
        out[OFF_ENC + 2] = 0.f;
        out[OFF_ENC + ENC_COUNT - 1] = 0.f;
    }
}

// ---------------------------------------------------------------------------
// Outputs: one warp per row. quantized = emb[idx] (exact gather),
// quantized_st = fl(x + fl(q - x)), one-hot scatter, histogram.
// ---------------------------------------------------------------------------
__global__ __launch_bounds__(256)
void vq_outputs(const float* __restrict__ xall, const float* __restrict__ emb,
                float* __restrict__ out) {
    int warp = threadIdx.x >> 5;
    int lane = threadIdx.x & 31;
    int row  = blockIdx.x * 8 + warp;
    int idx  = g_idx[row];

    if (lane == 0) atomicAdd(&g_counts[idx], 1);

    const float2* q2 = (const float2*)(emb  + (size_t)idx * DIM);
    const float2* x2 = (const float2*)(xall + (size_t)row * DIM);
    float2 q  = q2[lane];
    float2 xv = x2[lane];
    float2 st;
    st.x = __fadd_rn(xv.x, __fadd_rn(q.x, -xv.x));
    st.y = __fadd_rn(xv.y, __fadd_rn(q.y, -xv.y));
    ((float2*)(out + OFF_QST   + (size_t)row * DIM))[lane] = st;
    ((float2*)(out + OFF_QORIG + (size_t)row * DIM))[lane] = q;

    if (lane == (idx >> 5))
        out[OFF_ENC + (size_t)row * K_EMB + idx] = 1.0f;
}

// ---------------------------------------------------------------------------
// Perplexity from exact integer histogram.
// ---------------------------------------------------------------------------
__global__ void vq_perplexity(float* __restrict__ out) {
    __shared__ double s[256];
    double local = 0.0;
    for (int k = threadIdx.x; k < K_EMB; k += 256) {
        double p = (double)g_counts[k] * (1.0 / 131072.0);
        local += p * log(p + 1e-10);
    }
    s[threadIdx.x] = local;
    __syncthreads();
    for (int off = 128; off > 0; off >>= 1) {
        if (threadIdx.x < off) s[threadIdx.x] += s[threadIdx.x + off];
        __syncthreads();
    }
    if (threadIdx.x == 0) out[OFF_PERP] = (float)exp(-s[0]);
}

// ---------------------------------------------------------------------------
extern "C" void kernel_launch(void* const* d_in, const int* in_sizes, int n_in,
                              void* d_out, int out_size) {
    const float* x   = (const float*)d_in[0];
    const float* emb = (const float*)d_in[1];
    float* out = (float*)d_out;

    vq_setup<<<4, 256>>>(emb);
    vq_argmin<<<N_ROWS / 256, 256>>>(x, emb);
    vq_exact<<<512, 256>>>(x, emb);
    vq_zero_enc<<<2048, 256>>>(out);
    vq_outputs<<<N_ROWS / 8, 256>>>(x, emb, out);
    vq_perplexity<<<1, 256>>>(out);
}

// round 2
// speedup vs baseline: 2.1398x; 2.1398x over previous
#include <cuda_runtime.h>
#include <math.h>

#define N_ROWS 131072
#define DIM 64
#define K_EMB 1024

// Output layout (tuple order: quantized_st, quantized_original, perplexity, encodings)
#define OFF_QST   0
#define OFF_QORIG 8388608
#define OFF_PERP  16777216
#define OFF_ENC   16777217
#define ENC_COUNT ((size_t)N_ROWS * K_EMB)   // 134217728

__device__ int   g_idx[N_ROWS];
__device__ int4  g_cand[N_ROWS];
__device__ float g_b32[K_EMB];
__device__ int   g_counts[K_EMB];
__device__ int   g_flagged[N_ROWS];
__device__ int   g_nflag;

// Packed f32x2 helpers (sm_103a; ptxas won't auto-fuse — PTX only)
__device__ __forceinline__ unsigned long long fma2(unsigned long long a,
                                                   unsigned long long b,
                                                   unsigned long long c) {
    unsigned long long d;
    asm("fma.rn.f32x2 %0, %1, %2, %3;" : "=l"(d) : "l"(a), "l"(b), "l"(c));
    return d;
}
__device__ __forceinline__ unsigned long long add2(unsigned long long a,
                                                   unsigned long long b) {
    unsigned long long d;
    asm("add.rn.f32x2 %0, %1, %2;" : "=l"(d) : "l"(a), "l"(b));
    return d;
}
__device__ __forceinline__ float lo32(unsigned long long v) {
    return __uint_as_float((unsigned)v);
}
__device__ __forceinline__ float hi32(unsigned long long v) {
    return __uint_as_float((unsigned)(v >> 32));
}

// ---------------------------------------------------------------------------
// Setup: per-embedding ||e||^2 (fp64 -> fp32), zero histogram + flag counter.
// ---------------------------------------------------------------------------
__global__ void vq_setup(const float* __restrict__ emb) {
    int k = blockIdx.x * blockDim.x + threadIdx.x;
    if (k == 0) g_nflag = 0;
    if (k < K_EMB) {
        const float* e = emb + (size_t)k * DIM;
        double s = 0.0;
        #pragma unroll
        for (int j = 0; j < DIM; j++) { double v = (double)e[j]; s += v * v; }
        g_b32[k] = (float)s;
        g_counts[k] = 0;
    }
}

// ---------------------------------------------------------------------------
// Main argmin: one thread per row, x row in 32 packed b64 regs, embeddings
// streamed through smem in 128-row chunks. Inner dot uses fma.rn.f32x2
// (2 FMAs per fma-pipe slot), 4 packed chains. Distance replicates the
// reference rounding: d = fl(fl(a+b) - fl(2m)). Branchless sorted top-4
// (SEL ops on the ALU pipe, overlapped under the FMA-pipe bound).
// Rows whose top-2 margin <= ~8 ulps are flagged for exact re-rank.
// ---------------------------------------------------------------------------
__global__ __launch_bounds__(256, 2)
void vq_argmin(const float* __restrict__ xall, const float* __restrict__ emb) {
    __shared__ ulonglong2 es[128 * 16];   // 128 embeddings x 64 floats = 32 KB
    __shared__ float      bs[128];

    int row = blockIdx.x * 256 + threadIdx.x;

    unsigned long long xp[32];
    {
        const ulonglong2* xr = (const ulonglong2*)(xall + (size_t)row * DIM);
        #pragma unroll
        for (int i = 0; i < 16; i++) {
            ulonglong2 v = xr[i];
            xp[2*i]   = v.x;
            xp[2*i+1] = v.y;
        }
    }
    // a32 = fp32(exact ||x||^2); any fixed ulp offset vs the reference's fp32
    // sum shifts all distances uniformly and cannot change the argmin.
    double ad = 0.0;
    #pragma unroll
    for (int j = 0; j < 32; j++) {
        double v0 = (double)lo32(xp[j]);
        double v1 = (double)hi32(xp[j]);
        ad += v0 * v0 + v1 * v1;
    }
    float a32 = (float)ad;

    float d1 = 3.4e38f, d2 = 3.4e38f, d3 = 3.4e38f, d4 = 3.4e38f;
    int   i1 = 0, i2 = 0, i3 = 0, i4 = 0;

    for (int kb = 0; kb < K_EMB; kb += 128) {
        __syncthreads();
        const ulonglong2* src = (const ulonglong2*)(emb + (size_t)kb * DIM);
        for (int t = threadIdx.x; t < 2048; t += 256) es[t] = src[t];
        if (threadIdx.x < 128) bs[threadIdx.x] = g_b32[kb + threadIdx.x];
        __syncthreads();

        #pragma unroll 2
        for (int kk = 0; kk < 128; kk++) {
            const ulonglong2* ev = es + kk * 16;
            unsigned long long a0 = 0ull, a1 = 0ull, a2 = 0ull, a3 = 0ull;
            #pragma unroll
            for (int i = 0; i < 16; i += 2) {
                ulonglong2 ea = ev[i];
                ulonglong2 eb = ev[i + 1];
                a0 = fma2(xp[2*i],     ea.x, a0);
                a1 = fma2(xp[2*i + 1], ea.y, a1);
                a2 = fma2(xp[2*i + 2], eb.x, a2);
                a3 = fma2(xp[2*i + 3], eb.y, a3);
            }
            unsigned long long s01 = add2(a0, a1);
            unsigned long long s23 = add2(a2, a3);
            unsigned long long s   = add2(s01, s23);
            float m = __fadd_rn(lo32(s), hi32(s));
            float t = __fadd_rn(a32, bs[kk]);              // fl(a+b)
            float d = __fadd_rn(t, -__fmul_rn(2.0f, m));   // fl(t - 2m)

            int k = kb + kk;
            bool b1 = d < d1, b2 = d < d2, b3 = d < d3, b4 = d < d4;
            float nd4 = b4 ? (b3 ? d3 : d) : d4;  int ni4 = b4 ? (b3 ? i3 : k) : i4;
            float nd3 = b3 ? (b2 ? d2 : d) : d3;  int ni3 = b3 ? (b2 ? i2 : k) : i3;
            float nd2 = b2 ? (b1 ? d1 : d) : d2;  int ni2 = b2 ? (b1 ? i1 : k) : i2;
            float nd1 = b1 ? d : d1;              int ni1 = b1 ? k : i1;
            d1 = nd1; d2 = nd2; d3 = nd3; d4 = nd4;
            i1 = ni1; i2 = ni2; i3 = ni3; i4 = ni4;
        }
    }
    g_idx[row]  = i1;
    g_cand[row] = make_int4(i1, i2, i3, i4);

    // Flag near-ties: margin within ~8 ulps of the distance magnitude
    // (grid step of the final rounding is ulp(a32+b) ~ ulp(a32)).
    float thr = a32 * 9.536743e-7f;   // 8 * 2^-23 * a32
    if (!((d2 - d1) > thr)) {
        int p = atomicAdd(&g_nflag, 1);
        if (p < N_ROWS) g_flagged[p] = row;
    }
}

// ---------------------------------------------------------------------------
// Exact re-rank of flagged rows: compensated Dot2 (~correctly rounded fp32
// dot) for the 4 candidates only; same rounding chain; lowest-index tiebreak.
// One warp per flagged row; lanes 0-3 own one candidate each.
// ---------------------------------------------------------------------------
__global__ __launch_bounds__(256)
void vq_exact(const float* __restrict__ xall, const float* __restrict__ emb) {
    int nf = g_nflag;
    if (nf > N_ROWS) nf = N_ROWS;

    int lane  = threadIdx.x & 31;
    int warp  = (blockIdx.x * blockDim.x + threadIdx.x) >> 5;
    int nwarp = (gridDim.x * blockDim.x) >> 5;

    for (int f = warp; f < nf; f += nwarp) {
        int row = g_flagged[f];
        int4 cand = g_cand[row];
        int k = (lane == 0) ? cand.x : (lane == 1) ? cand.y
              : (lane == 2) ? cand.z : cand.w;

        float bestd = 3.4e38f;
        int   besti = 0x7fffffff;
        if (lane < 4) {
            const float* x = xall + (size_t)row * DIM;
            const float* e = emb  + (size_t)k * DIM;
            double ad = 0.0;
            float s = 0.f, c = 0.f;
            #pragma unroll
            for (int j = 0; j < DIM; j++) {
                float xv = __ldg(x + j), ev = __ldg(e + j);
                ad += (double)xv * (double)xv;
                float p  = __fmul_rn(xv, ev);
                float pe = fmaf(xv, ev, -p);            // exact product error
                float t  = __fadd_rn(s, p);             // TwoSum (Knuth)
                float z  = __fadd_rn(t, -s);
                float se = __fadd_rn(__fadd_rn(s, -__fadd_rn(t, -z)),
                                     __fadd_rn(p, -z));
                s = t;
                c = __fadd_rn(c, __fadd_rn(pe, se));
            }
            float a32 = (float)ad;
            float m  = __fadd_rn(s, c);                 // ~correctly rounded dot
            float t2 = __fadd_rn(a32, g_b32[k]);
            bestd = __fadd_rn(t2, -__fmul_rn(2.0f, m));
            besti = k;
        }
        #pragma unroll
        for (int off = 2; off > 0; off >>= 1) {
            float od = __shfl_down_sync(0xffffffffu, bestd, off);
            int   oi = __shfl_down_sync(0xffffffffu, besti, off);
            if (od < bestd || (od == bestd && oi < besti)) { bestd = od; besti = oi; }
        }
        if (lane == 0) g_idx[row] = besti;
    }
}

// ---------------------------------------------------------------------------
// Zero the encodings region (misaligned start: 3 scalar head + float4 body
// + 1 scalar tail).
// ---------------------------------------------------------------------------
__global__ void vq_zero_enc(float* __restrict__ out) {
    float4* base = (float4*)(out + OFF_ENC + 3);       // element 16777220: 16B-aligned
    const size_t n4 = (ENC_COUNT - 3 - 1) / 4;         // 33554431 float4s
    size_t i      = (size_t)blockIdx.x * blockDim.x + threadIdx.x;
    size_t stride = (size_t)gridDim.x * blockDim.x;
    float4 z = make_float4(0.f, 0.f, 0.f, 0.f);
    for (; i < n4; i += stride) base[i] = z;
    if (blockIdx.x == 0 && threadIdx.x == 0) {
        out[OFF_ENC + 0] = 0.f;
        out[OFF_ENC + 1] = 0.f;
        out[OFF_ENC + 2] = 0.f;
        out[OFF_ENC + ENC_COUNT - 1] = 0.f;
    }
}

// ---------------------------------------------------------------------------
// Outputs: one warp per row. quantized = emb[idx] (exact gather),
// quantized_st = fl(x + fl(q - x)), one-hot scatter, histogram.
// ---------------------------------------------------------------------------
__global__ __launch_bounds__(256)
void vq_outputs(const float* __restrict__ xall, const float* __restrict__ emb,
                float* __restrict__ out) {
    int warp = threadIdx.x >> 5;
    int lane = threadIdx.x & 31;
    int row  = blockIdx.x * 8 + warp;
    int idx  = g_idx[row];

    if (lane == 0) atomicAdd(&g_counts[idx], 1);

    const float2* q2 = (const float2*)(emb  + (size_t)idx * DIM);
    const float2* x2 = (const float2*)(xall + (size_t)row * DIM);
    float2 q  = q2[lane];
    float2 xv = x2[lane];
    float2 st;
    st.x = __fadd_rn(xv.x, __fadd_rn(q.x, -xv.x));
    st.y = __fadd_rn(xv.y, __fadd_rn(q.y, -xv.y));
    ((float2*)(out + OFF_QST   + (size_t)row * DIM))[lane] = st;
    ((float2*)(out + OFF_QORIG + (size_t)row * DIM))[lane] = q;

    if (lane == (idx >> 5))
        out[OFF_ENC + (size_t)row * K_EMB + idx] = 1.0f;
}

// ---------------------------------------------------------------------------
// Perplexity from exact integer histogram.
// ---------------------------------------------------------------------------
__global__ void vq_perplexity(float* __restrict__ out) {
    __shared__ double s[256];
    double local = 0.0;
    for (int k = threadIdx.x; k < K_EMB; k += 256) {
        double p = (double)g_counts[k] * (1.0 / 131072.0);
        local += p * log(p + 1e-10);
    }
    s[threadIdx.x] = local;
    __syncthreads();
    for (int off = 128; off > 0; off >>= 1) {
        if (threadIdx.x < off) s[threadIdx.x] += s[threadIdx.x + off];
        __syncthreads();
    }
    if (threadIdx.x == 0) out[OFF_PERP] = (float)exp(-s[0]);
}

// ---------------------------------------------------------------------------
extern "C" void kernel_launch(void* const* d_in, const int* in_sizes, int n_in,
                              void* d_out, int out_size) {
    const float* x   = (const float*)d_in[0];
    const float* emb = (const float*)d_in[1];
    float* out = (float*)d_out;

    vq_setup<<<4, 256>>>(emb);
    vq_argmin<<<N_ROWS / 256, 256>>>(x, emb);
    vq_exact<<<1024, 256>>>(x, emb);
    vq_zero_enc<<<4096, 256>>>(out);
    vq_outputs<<<N_ROWS / 8, 256>>>(x, emb, out);
    vq_perplexity<<<1, 256>>>(out);
}

// round 4
// speedup vs baseline: 3.6852x; 1.7222x over previous
#include <cuda_runtime.h>
#include <cuda_bf16.h>
#include <math.h>

#define N_ROWS 131072
#define DIM 64
#define K_EMB 1024
#define KCAT 192            // [xh, xh, xl] . [eh, el, eh]

// Output layout (tuple order: quantized_st, quantized_original, perplexity, encodings)
#define OFF_QST   0
#define OFF_QORIG 8388608
#define OFF_PERP  16777216
#define OFF_ENC   16777217
#define ENC_COUNT ((size_t)N_ROWS * K_EMB)

__device__ int   g_idx[N_ROWS];
__device__ float g_b32[K_EMB];
__device__ float g_a32[N_ROWS];
__device__ int   g_counts[K_EMB];
__device__ int   g_flagged[N_ROWS];
__device__ int   g_nflag;

// bf16-split operands, row-major [row][192] (384 B/row, 16B-aligned)
__device__ __align__(16) unsigned short g_x_cat[(size_t)N_ROWS * KCAT];
__device__ __align__(16) unsigned short g_e_cat[(size_t)K_EMB * KCAT];
// per (row, ntile) partial results: {d1, d2, bits(i1), bits(i2)}
__device__ float4 g_part[(size_t)N_ROWS * 8];

// ---------------------------------------------------------------------------
// sm_80-era tensor helpers (compile under compute_103: no 'a'-only features)
// ---------------------------------------------------------------------------
__device__ __forceinline__ unsigned smem_u32(const void* p) {
    unsigned a;
    asm("{ .reg .u64 t; cvta.to.shared.u64 t, %1; cvt.u32.u64 %0, t; }"
        : "=r"(a) : "l"(p));
    return a;
}
__device__ __forceinline__ void ldsm4(unsigned* r, unsigned addr) {
    asm volatile("ldmatrix.sync.aligned.m8n8.x4.shared.b16 {%0,%1,%2,%3}, [%4];"
                 : "=r"(r[0]), "=r"(r[1]), "=r"(r[2]), "=r"(r[3]) : "r"(addr));
}
__device__ __forceinline__ void mma_bf16(float* d, const unsigned* a, const unsigned* b) {
    asm volatile(
        "mma.sync.aligned.m16n8k16.row.col.f32.bf16.bf16.f32 "
        "{%0,%1,%2,%3}, {%4,%5,%6,%7}, {%8,%9}, {%0,%1,%2,%3};"
        : "+f"(d[0]), "+f"(d[1]), "+f"(d[2]), "+f"(d[3])
        : "r"(a[0]), "r"(a[1]), "r"(a[2]), "r"(a[3]), "r"(b[0]), "r"(b[1]));
}

// ---------------------------------------------------------------------------
// Convert embeddings: warp per code row. Writes [eh, el, eh] bf16, b32 (exact
// ||e||^2 -> fp32), zeroes counts + nflag.
// ---------------------------------------------------------------------------
__global__ void vq_convert_emb(const float* __restrict__ emb) {
    int lane = threadIdx.x & 31;
    int row  = (blockIdx.x * blockDim.x + threadIdx.x) >> 5;
    if (blockIdx.x == 0 && threadIdx.x == 0) g_nflag = 0;
    if (row >= K_EMB) return;

    float2 v = ((const float2*)(emb + (size_t)row * DIM))[lane];
    __nv_bfloat16 h0 = __float2bfloat16_rn(v.x);
    __nv_bfloat16 h1 = __float2bfloat16_rn(v.y);
    __nv_bfloat16 l0 = __float2bfloat16_rn(__fadd_rn(v.x, -__bfloat162float(h0)));
    __nv_bfloat16 l1 = __float2bfloat16_rn(__fadd_rn(v.y, -__bfloat162float(h1)));
    unsigned hp = ((unsigned)__bfloat16_as_ushort(h1) << 16) | __bfloat16_as_ushort(h0);
    unsigned lp = ((unsigned)__bfloat16_as_ushort(l1) << 16) | __bfloat16_as_ushort(l0);
    unsigned* o = (unsigned*)(g_e_cat + (size_t)row * KCAT);
    o[lane]      = hp;   // eh
    o[32 + lane] = lp;   // el
    o[64 + lane] = hp;   // eh

    double s = (double)v.x * v.x + (double)v.y * v.y;
    #pragma unroll
    for (int off = 16; off > 0; off >>= 1)
        s += __shfl_down_sync(0xffffffffu, s, off);
    if (lane == 0) { g_b32[row] = (float)s; g_counts[row] = 0; }
}

// ---------------------------------------------------------------------------
// Convert inputs: warp per row. Writes [xh, xh, xl] bf16 and a32.
// ---------------------------------------------------------------------------
__global__ void vq_convert_x(const float* __restrict__ xall) {
    int lane = threadIdx.x & 31;
    int row  = (blockIdx.x * blockDim.x + threadIdx.x) >> 5;

    float2 v = ((const float2*)(xall + (size_t)row * DIM))[lane];
    __nv_bfloat16 h0 = __float2bfloat16_rn(v.x);
    __nv_bfloat16 h1 = __float2bfloat16_rn(v.y);
    __nv_bfloat16 l0 = __float2bfloat16_rn(__fadd_rn(v.x, -__bfloat162float(h0)));
    __nv_bfloat16 l1 = __float2bfloat16_rn(__fadd_rn(v.y, -__bfloat162float(h1)));
    unsigned hp = ((unsigned)__bfloat16_as_ushort(h1) << 16) | __bfloat16_as_ushort(h0);
    unsigned lp = ((unsigned)__bfloat16_as_ushort(l1) << 16) | __bfloat16_as_ushort(l0);
    unsigned* o = (unsigned*)(g_x_cat + (size_t)row * KCAT);
    o[lane]      = hp;   // xh
    o[32 + lane] = hp;   // xh
    o[64 + lane] = lp;   // xl

    double s = (double)v.x * v.x + (double)v.y * v.y;
    #pragma unroll
    for (int off = 16; off > 0; off >>= 1)
        s += __shfl_down_sync(0xffffffffu, s, off);
    if (lane == 0) g_a32[row] = (float)s;
}

// ---------------------------------------------------------------------------
// HMMA distance + top-2: one CTA = 128 rows (mtile), loops 8 ntiles of 128
// codes. A staged once (swizzled), B streamed per ntile. Warp w owns rows
// 16w..16w+15 across all 128 codes; accumulators in registers.
// SMEM: [0:4096) b32, [4096:+48K) A, [53248:+48K) B. Total 102400 B.
// ---------------------------------------------------------------------------
#define SM_A 4096
#define SM_B 53248
#define SM_TOTAL 102400

// swizzled byte offset within a tile for (row r, 16B-chunk c):
// chunk's low 3 bits XOR row's low 3 bits -> ldmatrix conflict-free
#define SWZ_OFF(r, c) ((r) * 384 + ((((c) & 0x18) | (((c) & 7) ^ ((r) & 7))) << 4))

__global__ __launch_bounds__(256, 2) void vq_mma() {
    extern __shared__ char smem[];
    float* bs = (float*)smem;
    unsigned sbase = smem_u32(smem);
    int tid  = threadIdx.x;
    int wid  = tid >> 5;
    int lane = tid & 31;
    int l7   = lane & 7;
    int mtile = blockIdx.x;

    for (int i = tid; i < K_EMB; i += 256) bs[i] = g_b32[i];
    {
        const uint4* xa = (const uint4*)g_x_cat + (size_t)mtile * 128 * 24;
        for (int i = tid; i < 3072; i += 256) {
            int r = i / 24, c = i % 24;
            *(uint4*)(smem + SM_A + SWZ_OFF(r, c)) = xa[i];
        }
    }

    int rlo = wid * 16 + (lane >> 2);
    float a32lo = g_a32[mtile * 128 + rlo];
    float a32hi = g_a32[mtile * 128 + rlo + 8];

    // ldmatrix per-lane address components
    int a_r  = wid * 16 + ((lane >> 3) & 1) * 8 + l7;   // A: rowhalf=bit3
    int a_ch = (lane >> 4) & 1;                          //    khalf=bit4
    unsigned a_base = sbase + SM_A + a_r * 384;
    int b_rb = ((lane >> 4) & 1) * 8 + l7;               // B: rowhalf=bit4
    int b_ch = (lane >> 3) & 1;                          //    khalf=bit3
    unsigned b_base = sbase + SM_B + b_rb * 384;

    for (int nt = 0; nt < 8; nt++) {
        __syncthreads();
        const uint4* eb = (const uint4*)g_e_cat + (size_t)nt * 128 * 24;
        for (int i = tid; i < 3072; i += 256) {
            int r = i / 24, c = i % 24;
            *(uint4*)(smem + SM_B + SWZ_OFF(r, c)) = eb[i];
        }
        __syncthreads();

        float acc[16][4];
        #pragma unroll
        for (int nb = 0; nb < 16; nb++) {
            acc[nb][0] = 0.f; acc[nb][1] = 0.f; acc[nb][2] = 0.f; acc[nb][3] = 0.f;
        }

        #pragma unroll
        for (int ks = 0; ks < 12; ks++) {
            unsigned af[4];
            int ca = 2 * ks + a_ch;
            ldsm4(af, a_base + ((((ca & 0x18) | ((ca & 7) ^ l7))) << 4));
            int cb = 2 * ks + b_ch;
            unsigned boff = b_base + ((((cb & 0x18) | ((cb & 7) ^ l7))) << 4);
            #pragma unroll
            for (int j = 0; j < 8; j++) {
                unsigned bf[4];
                ldsm4(bf, boff + j * 6144);       // 16 rows * 384 B
                mma_bf16(acc[2*j],     af, bf);
                mma_bf16(acc[2*j + 1], af, bf + 2);
            }
        }

        // Epilogue: d = fl(fl(a32+b) - 2m); top-2 per row; quad-merge.
        float d1a = 3.4e38f, d2a = 3.4e38f; int i1a = 0, i2a = 0;  // row lo
        float d1b = 3.4e38f, d2b = 3.4e38f; int i1b = 0, i2b = 0;  // row hi
        int colp = nt * 128 + (lane & 3) * 2;
        #pragma unroll
        for (int nb = 0; nb < 16; nb++) {
            float2 bv = *(float2*)&bs[nt * 128 + nb * 8 + (lane & 3) * 2];
            int k0 = colp + nb * 8;
            float d;
            bool c1, c2;
            d = fmaf(acc[nb][0], -2.0f, __fadd_rn(a32lo, bv.x));
            c1 = d < d1a; c2 = d < d2a;
            d2a = c2 ? (c1 ? d1a : d) : d2a; i2a = c2 ? (c1 ? i1a : k0) : i2a;
            d1a = c1 ? d : d1a;              i1a = c1 ? k0 : i1a;
            d = fmaf(acc[nb][1], -2.0f, __fadd_rn(a32lo, bv.y));
            c1 = d < d1a; c2 = d < d2a;
            d2a = c2 ? (c1 ? d1a : d) : d2a; i2a = c2 ? (c1 ? i1a : k0 + 1) : i2a;
            d1a = c1 ? d : d1a;              i1a = c1 ? k0 + 1 : i1a;
            d = fmaf(acc[nb][2], -2.0f, __fadd_rn(a32hi, bv.x));
            c1 = d < d1b; c2 = d < d2b;
            d2b = c2 ? (c1 ? d1b : d) : d2b; i2b = c2 ? (c1 ? i1b : k0) : i2b;
            d1b = c1 ? d : d1b;              i1b = c1 ? k0 : i1b;
            d = fmaf(acc[nb][3], -2.0f, __fadd_rn(a32hi, bv.y));
            c1 = d < d1b; c2 = d < d2b;
            d2b = c2 ? (c1 ? d1b : d) : d2b; i2b = c2 ? (c1 ? i1b : k0 + 1) : i2b;
            d1b = c1 ? d : d1b;              i1b = c1 ? k0 + 1 : i1b;
        }
        // merge across the 4 lanes sharing each row (lowest-index wins ties)
        #pragma unroll
        for (int m = 1; m <= 2; m <<= 1) {
            float od1 = __shfl_xor_sync(0xffffffffu, d1a, m);
            int   oi1 = __shfl_xor_sync(0xffffffffu, i1a, m);
            float od2 = __shfl_xor_sync(0xffffffffu, d2a, m);
            int   oi2 = __shfl_xor_sync(0xffffffffu, i2a, m);
            if (od1 < d1a || (od1 == d1a && oi1 < i1a)) {
                float t = d1a; int ti = i1a;
                d1a = od1; i1a = oi1;
                if (od2 < t || (od2 == t && oi2 < ti)) { d2a = od2; i2a = oi2; }
                else                                   { d2a = t;   i2a = ti; }
            } else if (od1 < d2a || (od1 == d2a && oi1 < i2a)) {
                d2a = od1; i2a = oi1;
            }
            od1 = __shfl_xor_sync(0xffffffffu, d1b, m);
            oi1 = __shfl_xor_sync(0xffffffffu, i1b, m);
            od2 = __shfl_xor_sync(0xffffffffu, d2b, m);
            oi2 = __shfl_xor_sync(0xffffffffu, i2b, m);
            if (od1 < d1b || (od1 == d1b && oi1 < i1b)) {
                float t = d1b; int ti = i1b;
                d1b = od1; i1b = oi1;
                if (od2 < t || (od2 == t && oi2 < ti)) { d2b = od2; i2b = oi2; }
                else                                   { d2b = t;   i2b = ti; }
            } else if (od1 < d2b || (od1 == d2b && oi1 < i2b)) {
                d2b = od1; i2b = oi1;
            }
        }
        if ((lane & 3) == 0) {
            int rg = mtile * 128 + rlo;
            g_part[(size_t)rg * 8 + nt] =
                make_float4(d1a, d2a, __int_as_float(i1a), __int_as_float(i2a));
            g_part[(size_t)(rg + 8) * 8 + nt] =
                make_float4(d1b, d2b, __int_as_float(i1b), __int_as_float(i2b));
        }
    }
}

// ---------------------------------------------------------------------------
// Combine 8 partials per row -> global (d1,i1,d2); flag near-ties.
// ---------------------------------------------------------------------------
__global__ void vq_combine() {
    int row = blockIdx.x * blockDim.x + threadIdx.x;
    const float4* p = &g_part[(size_t)row * 8];
    float D1 = 3.4e38f, D2 = 3.4e38f;
    int I1 = 0;
    #pragma unroll
    for (int t = 0; t < 8; t++) {
        float4 q = p[t];
        if (q.x < D1) { D2 = fminf(D1, q.y); D1 = q.x; I1 = __float_as_int(q.z); }
        else          { D2 = fminf(D2, q.x); }
    }
    g_idx[row] = I1;
    float thr = g_a32[row] * 9.536743e-7f;   // 8 * 2^-23 * a32
    if (!((D2 - D1) > thr)) {
        int pos = atomicAdd(&g_nflag, 1);
        if (pos < N_ROWS) g_flagged[pos] = row;
    }
}

// ---------------------------------------------------------------------------
// Exact re-rank of flagged rows over the 16 per-tile candidates.
// ---------------------------------------------------------------------------
__global__ __launch_bounds__(256)
void vq_exact(const float* __restrict__ xall, const float* __restrict__ emb) {
    int nf = g_nflag;
    if (nf > N_ROWS) nf = N_ROWS;
    int lane  = threadIdx.x & 31;
    int warp  = (blockIdx.x * blockDim.x + threadIdx.x) >> 5;
    int nwarp = (gridDim.x * blockDim.x) >> 5;

    for (int f = warp; f < nf; f += nwarp) {
        int row = g_flagged[f];
        float bestd = 3.4e38f;
        int   besti = 0x7fffffff;
        if (lane < 16) {
            float4 q = g_part[(size_t)row * 8 + (lane >> 1)];
            int k = (lane & 1) ? __float_as_int(q.w) : __float_as_int(q.z);
            const float* x = xall + (size_t)row * DIM;
            const float* e = emb  + (size_t)k * DIM;
            double ad = 0.0;
            float s = 0.f, c = 0.f;
            #pragma unroll
            for (int j = 0; j < DIM; j++) {
                float xv = __ldg(x + j), ev = __ldg(e + j);
                ad += (double)xv * (double)xv;
                float pr = __fmul_rn(xv, ev);
                float pe = fmaf(xv, ev, -pr);
                float t  = __fadd_rn(s, pr);
                float z  = __fadd_rn(t, -s);
                float se = __fadd_rn(__fadd_rn(s, -__fadd_rn(t, -z)),
                                     __fadd_rn(pr, -z));
                s = t;
                c = __fadd_rn(c, __fadd_rn(pe, se));
            }
            float a32 = (float)ad;
            float m  = __fadd_rn(s, c);
            float t2 = __fadd_rn(a32, g_b32[k]);
            bestd = __fadd_rn(t2, -__fmul_rn(2.0f, m));
            besti = k;
        }
        #pragma unroll
        for (int off = 8; off > 0; off >>= 1) {
            float od = __shfl_down_sync(0xffffffffu, bestd, off);
            int   oi = __shfl_down_sync(0xffffffffu, besti, off);
            if (od < bestd || (od == bestd && oi < besti)) { bestd = od; besti = oi; }
        }
        if (lane == 0) g_idx[row] = besti;
    }
}

// ---------------------------------------------------------------------------
// Zero encodings (aligned float4 over the misaligned region).
// ---------------------------------------------------------------------------
__global__ void vq_zero_enc(float* __restrict__ out) {
    float4* base = (float4*)(out + OFF_ENC + 3);
    const size_t n4 = (ENC_COUNT - 3 - 1) / 4;
    size_t i      = (size_t)blockIdx.x * blockDim.x + threadIdx.x;
    size_t stride = (size_t)gridDim.x * blockDim.x;
    float4 z = make_float4(0.f, 0.f, 0.f, 0.f);
    for (; i < n4; i += stride) base[i] = z;
    if (blockIdx.x == 0 && threadIdx.x == 0) {
        out[OFF_ENC + 0] = 0.f;
        out[OFF_ENC + 1] = 0.f;
        out[OFF_ENC + 2] = 0.f;
        out[OFF_ENC + ENC_COUNT - 1] = 0.f;
    }
}

// ---------------------------------------------------------------------------
// Outputs: warp per row. quantized = emb[idx], st = fl(x + fl(q-x)),
// one-hot scatter, histogram.
// ---------------------------------------------------------------------------
__global__ __launch_bounds__(256)
void vq_outputs(const float* __restrict__ xall, const float* __restrict__ emb,
                float* __restrict__ out) {
    int warp = threadIdx.x >> 5;
    int lane = threadIdx.x & 31;
    int row  = blockIdx.x * 8 + warp;
    int idx  = g_idx[row];

    if (lane == 0) atomicAdd(&g_counts[idx], 1);

    float2 q  = ((const float2*)(emb  + (size_t)idx * DIM))[lane];
    float2 xv = ((const float2*)(xall + (size_t)row * DIM))[lane];
    float2 st;
    st.x = __fadd_rn(xv.x, __fadd_rn(q.x, -xv.x));
    st.y = __fadd_rn(xv.y, __fadd_rn(q.y, -xv.y));
    ((float2*)(out + OFF_QST   + (size_t)row * DIM))[lane] = st;
    ((float2*)(out + OFF_QORIG + (size_t)row * DIM))[lane] = q;

    if (lane == (idx >> 5))
        out[OFF_ENC + (size_t)row * K_EMB + idx] = 1.0f;
}

// ---------------------------------------------------------------------------
__global__ void vq_perplexity(float* __restrict__ out) {
    __shared__ double s[256];
    double local = 0.0;
    for (int k = threadIdx.x; k < K_EMB; k += 256) {
        double p = (double)g_counts[k] * (1.0 / 131072.0);
        local += p * log(p + 1e-10);
    }
    s[threadIdx.x] = local;
    __syncthreads();
    for (int off = 128; off > 0; off >>= 1) {
        if (threadIdx.x < off) s[threadIdx.x] += s[threadIdx.x + off];
        __syncthreads();
    }
    if (threadIdx.x == 0) out[OFF_PERP] = (float)exp(-s[0]);
}

// ---------------------------------------------------------------------------
extern "C" void kernel_launch(void* const* d_in, const int* in_sizes, int n_in,
                              void* d_out, int out_size) {
    const float* x   = (const float*)d_in[0];
    const float* emb = (const float*)d_in[1];
    float* out = (float*)d_out;

    cudaFuncSetAttribute(vq_mma, cudaFuncAttributeMaxDynamicSharedMemorySize, SM_TOTAL);

    vq_convert_emb<<<128, 256>>>(emb);
    vq_convert_x<<<16384, 256>>>(x);
    vq_mma<<<1024, 256, SM_TOTAL>>>();
    vq_combine<<<512, 256>>>();
    vq_exact<<<256, 256>>>(x, emb);
    vq_zero_enc<<<8192, 256>>>(out);
    vq_outputs<<<N_ROWS / 8, 256>>>(x, emb, out);
    vq_perplexity<<<1, 256>>>(out);
}

// round 6
// speedup vs baseline: 4.4741x; 1.2141x over previous
#include <cuda_runtime.h>
#include <cuda_bf16.h>
#include <math.h>

#define N_ROWS 131072
#define DIM 64
#define K_EMB 1024

// Output layout (tuple order: quantized_st, quantized_original, perplexity, encodings)
#define OFF_QST   0
#define OFF_QORIG 8388608
#define OFF_PERP  16777216
#define OFF_ENC   16777217
#define ENC_COUNT ((size_t)N_ROWS * K_EMB)

__device__ int   g_idx[N_ROWS];
__device__ float g_b32[K_EMB];
__device__ int   g_counts[K_EMB];
__device__ int   g_flagged[N_ROWS];
__device__ int   g_nflag;
// embeddings, bf16-split K=192 as [eh, eh, el], pre-swizzled per 128-row tile
// (8 tiles x 48KB). Paired with x = [xh, xl, xh]:
//   k 0-63: xh.eh,  k 64-127: xl.eh,  k 128-191: xh.el
__device__ uint4 g_e_swz[24576];
// candidate pool: per row 8 float4 = 16 (d, idx) candidates
__device__ float4 g_part[(size_t)N_ROWS * 8];

// ---------------------------------------------------------------------------
// helpers
// ---------------------------------------------------------------------------
__device__ __forceinline__ unsigned smem_u32(const void* p) {
    unsigned a;
    asm("{ .reg .u64 t; cvta.to.shared.u64 t, %1; cvt.u32.u64 %0, t; }"
        : "=r"(a) : "l"(p));
    return a;
}
__device__ __forceinline__ void ldsm4(unsigned* r, unsigned addr) {
    asm volatile("ldmatrix.sync.aligned.m8n8.x4.shared.b16 {%0,%1,%2,%3}, [%4];"
                 : "=r"(r[0]), "=r"(r[1]), "=r"(r[2]), "=r"(r[3]) : "r"(addr));
}
__device__ __forceinline__ void mma_bf16(float* d, const unsigned* a, const unsigned* b) {
    asm volatile(
        "mma.sync.aligned.m16n8k16.row.col.f32.bf16.bf16.f32 "
        "{%0,%1,%2,%3}, {%4,%5,%6,%7}, {%8,%9}, {%0,%1,%2,%3};"
        : "+f"(d[0]), "+f"(d[1]), "+f"(d[2]), "+f"(d[3])
        : "r"(a[0]), "r"(a[1]), "r"(a[2]), "r"(a[3]), "r"(b[0]), "r"(b[1]));
}
// pack two floats' bf16-high parts into one u32; also produce residual pack
__device__ __forceinline__ void split2(float x, float y, unsigned& hp, unsigned& lp) {
    __nv_bfloat16 hx = __float2bfloat16_rn(x);
    __nv_bfloat16 hy = __float2bfloat16_rn(y);
    __nv_bfloat16 lx = __float2bfloat16_rn(__fadd_rn(x, -__bfloat162float(hx)));
    __nv_bfloat16 ly = __float2bfloat16_rn(__fadd_rn(y, -__bfloat162float(hy)));
    hp = ((unsigned)__bfloat16_as_ushort(hy) << 16) | __bfloat16_as_ushort(hx);
    lp = ((unsigned)__bfloat16_as_ushort(ly) << 16) | __bfloat16_as_ushort(lx);
}

// swizzled byte offset within a 128-row x 24-chunk tile (chunk = 16B):
#define SWZ_OFF(r, c) ((r) * 384 + ((((c) & 0x18) | (((c) & 7) ^ ((r) & 7))) << 4))

// ---------------------------------------------------------------------------
// Convert embeddings -> pre-swizzled bf16-split tiles [eh, eh, el]; b32;
// zero counts/nflag. One warp per code row.
// ---------------------------------------------------------------------------
__global__ void vq_convert_emb(const float* __restrict__ emb) {
    int lane = threadIdx.x & 31;
    int row  = (blockIdx.x * blockDim.x + threadIdx.x) >> 5;
    if (blockIdx.x == 0 && threadIdx.x == 0) g_nflag = 0;
    if (row >= K_EMB) return;

    float2 v = ((const float2*)(emb + (size_t)row * DIM))[lane];
    unsigned hp, lp;
    split2(v.x, v.y, hp, lp);
    int tile = row >> 7, r = row & 127;
    unsigned char* tb = (unsigned char*)g_e_swz + tile * 49152;
    int c   = lane >> 2;
    int pos = (lane & 3) * 4;
    *(unsigned*)(tb + SWZ_OFF(r, c)      + pos) = hp;   // eh (pairs with xh)
    *(unsigned*)(tb + SWZ_OFF(r, 8 + c)  + pos) = hp;   // eh (pairs with xl)
    *(unsigned*)(tb + SWZ_OFF(r, 16 + c) + pos) = lp;   // el (pairs with xh)

    double s = (double)v.x * v.x + (double)v.y * v.y;
    #pragma unroll
    for (int off = 16; off > 0; off >>= 1)
        s += __shfl_down_sync(0xffffffffu, s, off);
    if (lane == 0) { g_b32[row] = (float)s; g_counts[row] = 0; }
}

// ---------------------------------------------------------------------------
// Fused convert-x + HMMA distance + top-2 + combine + flag.
// CTA = 128 rows; warps in 4x2 grid: wm (32 rows) x wn (64 codes).
// SMEM: bs[1024]f @0 (4KB), a32s[128]f @4096, A @5120 (48KB), B @54272 (48KB).
// ---------------------------------------------------------------------------
#define SM_A  5120
#define SM_B  54272
#define SM_TOTAL 103424

__global__ __launch_bounds__(256, 2) void vq_mma(const float* __restrict__ xall) {
    extern __shared__ char smem[];
    float* bs   = (float*)smem;
    float* a32s = (float*)(smem + 4096);
    unsigned sbase = smem_u32(smem);
    int tid  = threadIdx.x;
    int wid  = tid >> 5;
    int lane = tid & 31;
    int l7   = lane & 7;
    int wm   = wid & 3;       // 4 row-groups of 32
    int wn   = wid >> 2;      // 2 code-halves of 64
    int mtile = blockIdx.x;

    // Phase 0: bs fill + A convert-fill [xh, xl, xh] + a32
    for (int i = tid; i < K_EMB; i += 256) bs[i] = g_b32[i];
    {
        int r = tid >> 1, h = tid & 1;
        const float4* xr = (const float4*)(xall + ((size_t)(mtile * 128 + r)) * DIM + h * 32);
        double ss = 0.0;
        #pragma unroll
        for (int j = 0; j < 4; j++) {
            float4 f0 = xr[2 * j];
            float4 f1 = xr[2 * j + 1];
            ss += (double)f0.x * f0.x + (double)f0.y * f0.y
                + (double)f0.z * f0.z + (double)f0.w * f0.w
                + (double)f1.x * f1.x + (double)f1.y * f1.y
                + (double)f1.z * f1.z + (double)f1.w * f1.w;
            uint4 hp4, lp4;
            split2(f0.x, f0.y, hp4.x, lp4.x);
            split2(f0.z, f0.w, hp4.y, lp4.y);
            split2(f1.x, f1.y, hp4.z, lp4.z);
            split2(f1.z, f1.w, hp4.w, lp4.w);
            int c = h * 4 + j;
            *(uint4*)(smem + SM_A + SWZ_OFF(r, c))      = hp4;  // xh . eh
            *(uint4*)(smem + SM_A + SWZ_OFF(r, 8 + c))  = lp4;  // xl . eh
            *(uint4*)(smem + SM_A + SWZ_OFF(r, 16 + c)) = hp4;  // xh . el
        }
        ss += __shfl_xor_sync(0xffffffffu, ss, 1);
        if (h == 0) a32s[r] = (float)ss;
    }

    // ldmatrix base addresses
    int a_sub = ((lane >> 3) & 1) * 8 + l7;
    int a_ch  = (lane >> 4) & 1;
    unsigned abase0 = sbase + SM_A + (wm * 32 + a_sub) * 384;
    unsigned abase1 = abase0 + 16 * 384;
    int b_sub = ((lane >> 4) & 1) * 8 + l7;
    int b_ch  = (lane >> 3) & 1;
    unsigned bbase0 = sbase + SM_B + (wn * 64 + b_sub) * 384;

    int q    = lane >> 2;       // row-within-8 owner
    int cpos = (lane & 3) * 2;  // col pair within n8

    float a32r[4];
    float d1[4], d2[4];
    int   i1[4], i2[4];
    #pragma unroll
    for (int m = 0; m < 4; m++) { d1[m] = 3.4e38f; d2[m] = 3.4e38f; i1[m] = 0; i2[m] = 0; }

    for (int nt = 0; nt < 8; nt++) {
        __syncthreads();
        {
            const uint4* src = g_e_swz + nt * 3072;
            uint4* dst = (uint4*)(smem + SM_B);
            for (int i = tid; i < 3072; i += 256) dst[i] = src[i];
        }
        __syncthreads();
        if (nt == 0) {
            #pragma unroll
            for (int m = 0; m < 4; m++) a32r[m] = a32s[wm * 32 + q + m * 8];
        }

        float acc[2][8][4];
        #pragma unroll
        for (int t = 0; t < 2; t++)
            #pragma unroll
            for (int j = 0; j < 8; j++) {
                acc[t][j][0] = 0.f; acc[t][j][1] = 0.f;
                acc[t][j][2] = 0.f; acc[t][j][3] = 0.f;
            }

        #pragma unroll
        for (int ks = 0; ks < 12; ks++) {
            int ca = 2 * ks + a_ch;
            unsigned aoff = (((ca & 0x18) | ((ca & 7) ^ l7)) << 4);
            unsigned af0[4], af1[4];
            ldsm4(af0, abase0 + aoff);
            ldsm4(af1, abase1 + aoff);
            int cb = 2 * ks + b_ch;
            unsigned boff = (((cb & 0x18) | ((cb & 7) ^ l7)) << 4);
            #pragma unroll
            for (int cg = 0; cg < 4; cg++) {
                unsigned bf[4];
                ldsm4(bf, bbase0 + cg * (16 * 384) + boff);
                mma_bf16(acc[0][2 * cg],     af0, bf);
                mma_bf16(acc[0][2 * cg + 1], af0, bf + 2);
                mma_bf16(acc[1][2 * cg],     af1, bf);
                mma_bf16(acc[1][2 * cg + 1], af1, bf + 2);
            }
        }

        // epilogue: d = fl(fl(a32+b) - 2m); running per-lane top2 per row
        int kbase = nt * 128 + wn * 64 + cpos;
        #pragma unroll
        for (int j = 0; j < 8; j++) {
            float2 bv = *(float2*)&bs[nt * 128 + wn * 64 + j * 8 + cpos];
            int k0 = kbase + j * 8;
            #pragma unroll
            for (int t = 0; t < 2; t++) {
                #pragma unroll
                for (int rr = 0; rr < 2; rr++) {
                    int m = t * 2 + rr;
                    float ta = a32r[m];
                    float v0 = fmaf(acc[t][j][2 * rr],     -2.0f, __fadd_rn(ta, bv.x));
                    float v1 = fmaf(acc[t][j][2 * rr + 1], -2.0f, __fadd_rn(ta, bv.y));
                    bool c1 = v0 < d1[m], c2 = v0 < d2[m];
                    d2[m] = c2 ? (c1 ? d1[m] : v0) : d2[m];
                    i2[m] = c2 ? (c1 ? i1[m] : k0) : i2[m];
                    d1[m] = c1 ? v0 : d1[m];
                    i1[m] = c1 ? k0 : i1[m];
                    c1 = v1 < d1[m]; c2 = v1 < d2[m];
                    d2[m] = c2 ? (c1 ? d1[m] : v1) : d2[m];
                    i2[m] = c2 ? (c1 ? i1[m] : k0 + 1) : i2[m];
                    d1[m] = c1 ? v1 : d1[m];
                    i1[m] = c1 ? k0 + 1 : i1[m];
                }
            }
        }
    }

    // candidate pool: per lane, per row: (d1,d2,i1,i2)
    #pragma unroll
    for (int m = 0; m < 4; m++) {
        int row = mtile * 128 + wm * 32 + q + m * 8;
        g_part[(size_t)row * 8 + wn * 4 + (lane & 3)] =
            make_float4(d1[m], d2[m], __int_as_float(i1[m]), __int_as_float(i2[m]));
    }

    // quad merge (lanes sharing a row); lowest-index tie-break
    #pragma unroll
    for (int off = 1; off <= 2; off <<= 1) {
        #pragma unroll
        for (int m = 0; m < 4; m++) {
            float od1 = __shfl_xor_sync(0xffffffffu, d1[m], off);
            int   oi1 = __shfl_xor_sync(0xffffffffu, i1[m], off);
            float od2 = __shfl_xor_sync(0xffffffffu, d2[m], off);
            int   oi2 = __shfl_xor_sync(0xffffffffu, i2[m], off);
            if (od1 < d1[m] || (od1 == d1[m] && oi1 < i1[m])) {
                float t = d1[m]; int ti = i1[m];
                d1[m] = od1; i1[m] = oi1;
                if (od2 < t || (od2 == t && oi2 < ti)) { d2[m] = od2; i2[m] = oi2; }
                else                                   { d2[m] = t;   i2[m] = ti; }
            } else if (od1 < d2[m] || (od1 == d2[m] && oi1 < i2[m])) {
                d2[m] = od1; i2[m] = oi1;
            }
        }
    }

    // cross-half merge via smem (reuse B region)
    __syncthreads();
    float* md1 = (float*)(smem + SM_B);
    float* md2 = (float*)(smem + SM_B + 512);
    int*   mi1 = (int*)  (smem + SM_B + 1024);
    if (wn == 0 && (lane & 3) == 0) {
        #pragma unroll
        for (int m = 0; m < 4; m++) {
            int rl = wm * 32 + q + m * 8;
            md1[rl] = d1[m]; md2[rl] = d2[m]; mi1[rl] = i1[m];
        }
    }
    __syncthreads();
    if (wn == 1 && (lane & 3) == 0) {
        #pragma unroll
        for (int m = 0; m < 4; m++) {
            int rl  = wm * 32 + q + m * 8;
            int row = mtile * 128 + rl;
            float oa = md1[rl], oa2 = md2[rl];
            int   ia = mi1[rl];
            float D1, D2; int I1;
            if (d1[m] < oa) { D1 = d1[m]; I1 = i1[m]; D2 = fminf(oa, d2[m]); }
            else            { D1 = oa;    I1 = ia;    D2 = fminf(d1[m], oa2); }
            g_idx[row] = I1;
            float thr = a32r[m] * 9.536743e-7f;   // 8 * 2^-23 * a32
            if (!((D2 - D1) > thr)) {
                int pos = atomicAdd(&g_nflag, 1);
                if (pos < N_ROWS) g_flagged[pos] = row;
            }
        }
    }
}

// ---------------------------------------------------------------------------
// Exact re-rank of flagged rows over the 16 pooled candidates.
// ---------------------------------------------------------------------------
__global__ __launch_bounds__(256)
void vq_exact(const float* __restrict__ xall, const float* __restrict__ emb) {
    int nf = g_nflag;
    if (nf > N_ROWS) nf = N_ROWS;
    int lane  = threadIdx.x & 31;
    int warp  = (blockIdx.x * blockDim.x + threadIdx.x) >> 5;
    int nwarp = (gridDim.x * blockDim.x) >> 5;

    for (int f = warp; f < nf; f += nwarp) {
        int row = g_flagged[f];
        float bestd = 3.4e38f;
        int   besti = 0x7fffffff;
        if (lane < 16) {
            float4 qq = g_part[(size_t)row * 8 + (lane >> 1)];
            int k = (lane & 1) ? __float_as_int(qq.w) : __float_as_int(qq.z);
            const float* x = xall + (size_t)row * DIM;
            const float* e = emb  + (size_t)k * DIM;
            double ad = 0.0;
            float s = 0.f, c = 0.f;
            #pragma unroll
            for (int j = 0; j < DIM; j++) {
                float xv = __ldg(x + j), ev = __ldg(e + j);
                ad += (double)xv * (double)xv;
                float pr = __fmul_rn(xv, ev);
                float pe = fmaf(xv, ev, -pr);
                float t  = __fadd_rn(s, pr);
                float z  = __fadd_rn(t, -s);
                float se = __fadd_rn(__fadd_rn(s, -__fadd_rn(t, -z)),
                                     __fadd_rn(pr, -z));
                s = t;
                c = __fadd_rn(c, __fadd_rn(pe, se));
            }
            float a32 = (float)ad;
            float m  = __fadd_rn(s, c);
            float t2 = __fadd_rn(a32, g_b32[k]);
            bestd = __fadd_rn(t2, -__fmul_rn(2.0f, m));
            besti = k;
        }
        #pragma unroll
        for (int off = 8; off > 0; off >>= 1) {
            float od = __shfl_down_sync(0xffffffffu, bestd, off);
            int   oi = __shfl_down_sync(0xffffffffu, besti, off);
            if (od < bestd || (od == bestd && oi < besti)) { bestd = od; besti = oi; }
        }
        if (lane == 0) g_idx[row] = besti;
    }
}

// ---------------------------------------------------------------------------
// Fused outputs: warp per row. st/qorig + full one-hot row write + histogram.
// ---------------------------------------------------------------------------
__global__ __launch_bounds__(256)
void vq_outputs(const float* __restrict__ xall, const float* __restrict__ emb,
                float* __restrict__ out) {
    int warp = threadIdx.x >> 5;
    int lane = threadIdx.x & 31;
    int row  = blockIdx.x * 8 + warp;
    int idx  = g_idx[row];

    if (lane == 0) atomicAdd(&g_counts[idx], 1);

    float2 q  = ((const float2*)(emb  + (size_t)idx * DIM))[lane];
    float2 xv = ((const float2*)(xall + (size_t)row * DIM))[lane];
    float2 st;
    st.x = __fadd_rn(xv.x, __fadd_rn(q.x, -xv.x));
    st.y = __fadd_rn(xv.y, __fadd_rn(q.y, -xv.y));
    ((float2*)(out + OFF_QST   + (size_t)row * DIM))[lane] = st;
    ((float2*)(out + OFF_QORIG + (size_t)row * DIM))[lane] = q;

    // one-hot row: head (els 0-2), float4 body (els 3..1022), tail (el 1023)
    float* er = out + OFF_ENC + (size_t)row * K_EMB;
    if (lane < 3) er[lane] = (lane == idx) ? 1.0f : 0.0f;
    if (lane == 3) er[1023] = (idx == 1023) ? 1.0f : 0.0f;
    float4* body = (float4*)(er + 3);   // 16B-aligned
    for (int i = lane; i < 255; i += 32) {
        int k0 = 3 + i * 4;
        float4 v;
        v.x = (k0     == idx) ? 1.0f : 0.0f;
        v.y = (k0 + 1 == idx) ? 1.0f : 0.0f;
        v.z = (k0 + 2 == idx) ? 1.0f : 0.0f;
        v.w = (k0 + 3 == idx) ? 1.0f : 0.0f;
        body[i] = v;
    }
}

// ---------------------------------------------------------------------------
__global__ void vq_perplexity(float* __restrict__ out) {
    __shared__ double s[256];
    double local = 0.0;
    for (int k = threadIdx.x; k < K_EMB; k += 256) {
        double p = (double)g_counts[k] * (1.0 / 131072.0);
        local += p * log(p + 1e-10);
    }
    s[threadIdx.x] = local;
    __syncthreads();
    for (int off = 128; off > 0; off >>= 1) {
        if (threadIdx.x < off) s[threadIdx.x] += s[threadIdx.x + off];
        __syncthreads();
    }
    if (threadIdx.x == 0) out[OFF_PERP] = (float)exp(-s[0]);
}

// ---------------------------------------------------------------------------
extern "C" void kernel_launch(void* const* d_in, const int* in_sizes, int n_in,
                              void* d_out, int out_size) {
    const float* x   = (const float*)d_in[0];
    const float* emb = (const float*)d_in[1];
    float* out = (float*)d_out;

    cudaFuncSetAttribute(vq_mma, cudaFuncAttributeMaxDynamicSharedMemorySize, SM_TOTAL);

    vq_convert_emb<<<128, 256>>>(emb);
    vq_mma<<<1024, 256, SM_TOTAL>>>(x);
    vq_exact<<<256, 256>>>(x, emb);
    vq_outputs<<<N_ROWS / 8, 256>>>(x, emb, out);
    vq_perplexity<<<1, 256>>>(out);
}

// round 7
// speedup vs baseline: 4.6372x; 1.0365x over previous
#include <cuda_runtime.h>
#include <cuda_bf16.h>
#include <math.h>

#define N_ROWS 131072
#define DIM 64
#define K_EMB 1024

// Output layout (tuple order: quantized_st, quantized_original, perplexity, encodings)
#define OFF_QST   0
#define OFF_QORIG 8388608
#define OFF_PERP  16777216
#define OFF_ENC   16777217
#define ENC_COUNT ((size_t)N_ROWS * K_EMB)

__device__ int   g_idx[N_ROWS];
__device__ float g_b32[K_EMB];
__device__ int   g_counts[K_EMB];
__device__ int   g_flagged[N_ROWS];
__device__ int   g_nflag;
// embeddings, bf16-split K=192 as [eh, eh, el], pre-swizzled per 128-row tile
// (8 tiles x 48KB). Paired with x = [xh, xl, xh]:
//   k 0-63: xh.eh,  k 64-127: xl.eh,  k 128-191: xh.el
__device__ uint4 g_e_swz[24576];
// candidate pool: per row 8 float4 = 16 (d, idx) candidates
__device__ float4 g_part[(size_t)N_ROWS * 8];

// ---------------------------------------------------------------------------
// helpers
// ---------------------------------------------------------------------------
__device__ __forceinline__ unsigned smem_u32(const void* p) {
    unsigned a;
    asm("{ .reg .u64 t; cvta.to.shared.u64 t, %1; cvt.u32.u64 %0, t; }"
        : "=r"(a) : "l"(p));
    return a;
}
__device__ __forceinline__ void ldsm4(unsigned* r, unsigned addr) {
    asm volatile("ldmatrix.sync.aligned.m8n8.x4.shared.b16 {%0,%1,%2,%3}, [%4];"
                 : "=r"(r[0]), "=r"(r[1]), "=r"(r[2]), "=r"(r[3]) : "r"(addr));
}
__device__ __forceinline__ void mma_bf16(float* d, const unsigned* a, const unsigned* b) {
    asm volatile(
        "mma.sync.aligned.m16n8k16.row.col.f32.bf16.bf16.f32 "
        "{%0,%1,%2,%3}, {%4,%5,%6,%7}, {%8,%9}, {%0,%1,%2,%3};"
        : "+f"(d[0]), "+f"(d[1]), "+f"(d[2]), "+f"(d[3])
        : "r"(a[0]), "r"(a[1]), "r"(a[2]), "r"(a[3]), "r"(b[0]), "r"(b[1]));
}
// pack two floats' bf16-high parts into one u32; also produce residual pack
__device__ __forceinline__ void split2(float x, float y, unsigned& hp, unsigned& lp) {
    __nv_bfloat16 hx = __float2bfloat16_rn(x);
    __nv_bfloat16 hy = __float2bfloat16_rn(y);
    __nv_bfloat16 lx = __float2bfloat16_rn(__fadd_rn(x, -__bfloat162float(hx)));
    __nv_bfloat16 ly = __float2bfloat16_rn(__fadd_rn(y, -__bfloat162float(hy)));
    hp = ((unsigned)__bfloat16_as_ushort(hy) << 16) | __bfloat16_as_ushort(hx);
    lp = ((unsigned)__bfloat16_as_ushort(ly) << 16) | __bfloat16_as_ushort(lx);
}

// swizzled byte offset within a 128-row x 24-chunk tile (chunk = 16B):
#define SWZ_OFF(r, c) ((r) * 384 + ((((c) & 0x18) | (((c) & 7) ^ ((r) & 7))) << 4))

// ---------------------------------------------------------------------------
// Convert embeddings -> pre-swizzled bf16-split tiles [eh, eh, el]; b32;
// zero counts/nflag. One warp per code row.
// ---------------------------------------------------------------------------
__global__ void vq_convert_emb(const float* __restrict__ emb) {
    int lane = threadIdx.x & 31;
    int row  = (blockIdx.x * blockDim.x + threadIdx.x) >> 5;
    if (blockIdx.x == 0 && threadIdx.x == 0) g_nflag = 0;
    if (row >= K_EMB) return;

    float2 v = ((const float2*)(emb + (size_t)row * DIM))[lane];
    unsigned hp, lp;
    split2(v.x, v.y, hp, lp);
    int tile = row >> 7, r = row & 127;
    unsigned char* tb = (unsigned char*)g_e_swz + tile * 49152;
    int c   = lane >> 2;
    int pos = (lane & 3) * 4;
    *(unsigned*)(tb + SWZ_OFF(r, c)      + pos) = hp;   // eh (pairs with xh)
    *(unsigned*)(tb + SWZ_OFF(r, 8 + c)  + pos) = hp;   // eh (pairs with xl)
    *(unsigned*)(tb + SWZ_OFF(r, 16 + c) + pos) = lp;   // el (pairs with xh)

    double s = (double)v.x * v.x + (double)v.y * v.y;
    #pragma unroll
    for (int off = 16; off > 0; off >>= 1)
        s += __shfl_down_sync(0xffffffffu, s, off);
    if (lane == 0) { g_b32[row] = (float)s; g_counts[row] = 0; }
}

// ---------------------------------------------------------------------------
// Fused convert-x + HMMA distance + top-2 + combine + flag.
// CTA = 128 rows; warps in 4x2 grid: wm (32 rows) x wn (64 codes).
// Each ntile processed in two 32-code halves to keep acc at 32 regs/thread
// (avoids spills under the 128-reg cap of launch_bounds(256,2)).
// SMEM: bs[1024]f @0 (4KB), a32s[128]f @4096, A @5120 (48KB), B @54272 (48KB).
// ---------------------------------------------------------------------------
#define SM_A  5120
#define SM_B  54272
#define SM_TOTAL 103424

__global__ __launch_bounds__(256, 2) void vq_mma(const float* __restrict__ xall) {
    extern __shared__ char smem[];
    float* bs   = (float*)smem;
    float* a32s = (float*)(smem + 4096);
    unsigned sbase = smem_u32(smem);
    int tid  = threadIdx.x;
    int wid  = tid >> 5;
    int lane = tid & 31;
    int l7   = lane & 7;
    int wm   = wid & 3;       // 4 row-groups of 32
    int wn   = wid >> 2;      // 2 code-halves of 64
    int mtile = blockIdx.x;

    // Phase 0: bs fill + A convert-fill [xh, xl, xh] + a32
    for (int i = tid; i < K_EMB; i += 256) bs[i] = g_b32[i];
    {
        int r = tid >> 1, h = tid & 1;
        const float4* xr = (const float4*)(xall + ((size_t)(mtile * 128 + r)) * DIM + h * 32);
        double ss = 0.0;
        #pragma unroll
        for (int j = 0; j < 4; j++) {
            float4 f0 = xr[2 * j];
            float4 f1 = xr[2 * j + 1];
            ss += (double)f0.x * f0.x + (double)f0.y * f0.y
                + (double)f0.z * f0.z + (double)f0.w * f0.w
                + (double)f1.x * f1.x + (double)f1.y * f1.y
                + (double)f1.z * f1.z + (double)f1.w * f1.w;
            uint4 hp4, lp4;
            split2(f0.x, f0.y, hp4.x, lp4.x);
            split2(f0.z, f0.w, hp4.y, lp4.y);
            split2(f1.x, f1.y, hp4.z, lp4.z);
            split2(f1.z, f1.w, hp4.w, lp4.w);
            int c = h * 4 + j;
            *(uint4*)(smem + SM_A + SWZ_OFF(r, c))      = hp4;  // xh . eh
            *(uint4*)(smem + SM_A + SWZ_OFF(r, 8 + c))  = lp4;  // xl . eh
            *(uint4*)(smem + SM_A + SWZ_OFF(r, 16 + c)) = hp4;  // xh . el
        }
        ss += __shfl_xor_sync(0xffffffffu, ss, 1);
        if (h == 0) a32s[r] = (float)ss;
    }

    // ldmatrix base addresses
    int a_sub = ((lane >> 3) & 1) * 8 + l7;
    int a_ch  = (lane >> 4) & 1;
    unsigned abase0 = sbase + SM_A + (wm * 32 + a_sub) * 384;
    unsigned abase1 = abase0 + 16 * 384;
    int b_sub = ((lane >> 4) & 1) * 8 + l7;
    int b_ch  = (lane >> 3) & 1;
    unsigned bbase0 = sbase + SM_B + (wn * 64 + b_sub) * 384;

    int q    = lane >> 2;       // row-within-8 owner
    int cpos = (lane & 3) * 2;  // col pair within n8

    float a32r[4];
    float d1[4], d2[4];
    int   i1[4], i2[4];
    #pragma unroll
    for (int m = 0; m < 4; m++) { d1[m] = 3.4e38f; d2[m] = 3.4e38f; i1[m] = 0; i2[m] = 0; }

    for (int nt = 0; nt < 8; nt++) {
        __syncthreads();
        {
            const uint4* src = g_e_swz + nt * 3072;
            uint4* dst = (uint4*)(smem + SM_B);
            for (int i = tid; i < 3072; i += 256) dst[i] = src[i];
        }
        __syncthreads();
        if (nt == 0) {
            #pragma unroll
            for (int m = 0; m < 4; m++) a32r[m] = a32s[wm * 32 + q + m * 8];
        }

        #pragma unroll
        for (int half = 0; half < 2; half++) {
            float acc[2][4][4];
            #pragma unroll
            for (int t = 0; t < 2; t++)
                #pragma unroll
                for (int j = 0; j < 4; j++) {
                    acc[t][j][0] = 0.f; acc[t][j][1] = 0.f;
                    acc[t][j][2] = 0.f; acc[t][j][3] = 0.f;
                }

            #pragma unroll
            for (int ks = 0; ks < 12; ks++) {
                int ca = 2 * ks + a_ch;
                unsigned aoff = (((ca & 0x18) | ((ca & 7) ^ l7)) << 4);
                unsigned af0[4], af1[4];
                ldsm4(af0, abase0 + aoff);
                ldsm4(af1, abase1 + aoff);
                int cb = 2 * ks + b_ch;
                unsigned boff = (((cb & 0x18) | ((cb & 7) ^ l7)) << 4);
                #pragma unroll
                for (int g = 0; g < 2; g++) {
                    int cg = half * 2 + g;
                    unsigned bf[4];
                    ldsm4(bf, bbase0 + cg * (16 * 384) + boff);
                    mma_bf16(acc[0][2 * g],     af0, bf);
                    mma_bf16(acc[0][2 * g + 1], af0, bf + 2);
                    mma_bf16(acc[1][2 * g],     af1, bf);
                    mma_bf16(acc[1][2 * g + 1], af1, bf + 2);
                }
            }

            // epilogue: d = fl(fl(a32+b) - 2m); running per-lane top2 per row
            int colbase = nt * 128 + wn * 64 + half * 32;
            #pragma unroll
            for (int j = 0; j < 4; j++) {
                float2 bv = *(float2*)&bs[colbase + j * 8 + cpos];
                int k0 = colbase + j * 8 + cpos;
                #pragma unroll
                for (int t = 0; t < 2; t++) {
                    #pragma unroll
                    for (int rr = 0; rr < 2; rr++) {
                        int m = t * 2 + rr;
                        float ta = a32r[m];
                        float v0 = fmaf(acc[t][j][2 * rr],     -2.0f, __fadd_rn(ta, bv.x));
                        float v1 = fmaf(acc[t][j][2 * rr + 1], -2.0f, __fadd_rn(ta, bv.y));
                        bool c1 = v0 < d1[m], c2 = v0 < d2[m];
                        d2[m] = c2 ? (c1 ? d1[m] : v0) : d2[m];
                        i2[m] = c2 ? (c1 ? i1[m] : k0) : i2[m];
                        d1[m] = c1 ? v0 : d1[m];
                        i1[m] = c1 ? k0 : i1[m];
                        c1 = v1 < d1[m]; c2 = v1 < d2[m];
                        d2[m] = c2 ? (c1 ? d1[m] : v1) : d2[m];
                        i2[m] = c2 ? (c1 ? i1[m] : k0 + 1) : i2[m];
                        d1[m] = c1 ? v1 : d1[m];
                        i1[m] = c1 ? k0 + 1 : i1[m];
                    }
                }
            }
        }
    }

    // candidate pool: per lane, per row: (d1,d2,i1,i2)
    #pragma unroll
    for (int m = 0; m < 4; m++) {
        int row = mtile * 128 + wm * 32 + q + m * 8;
        g_part[(size_t)row * 8 + wn * 4 + (lane & 3)] =
            make_float4(d1[m], d2[m], __int_as_float(i1[m]), __int_as_float(i2[m]));
    }

    // quad merge (lanes sharing a row); lowest-index tie-break
    #pragma unroll
    for (int off = 1; off <= 2; off <<= 1) {
        #pragma unroll
        for (int m = 0; m < 4; m++) {
            float od1 = __shfl_xor_sync(0xffffffffu, d1[m], off);
            int   oi1 = __shfl_xor_sync(0xffffffffu, i1[m], off);
            float od2 = __shfl_xor_sync(0xffffffffu, d2[m], off);
            int   oi2 = __shfl_xor_sync(0xffffffffu, i2[m], off);
            if (od1 < d1[m] || (od1 == d1[m] && oi1 < i1[m])) {
                float t = d1[m]; int ti = i1[m];
                d1[m] = od1; i1[m] = oi1;
                if (od2 < t || (od2 == t && oi2 < ti)) { d2[m] = od2; i2[m] = oi2; }
                else                                   { d2[m] = t;   i2[m] = ti; }
            } else if (od1 < d2[m] || (od1 == d2[m] && oi1 < i2[m])) {
                d2[m] = od1; i2[m] = oi1;
            }
        }
    }

    // cross-half merge via smem (reuse B region)
    __syncthreads();
    float* md1 = (float*)(smem + SM_B);
    float* md2 = (float*)(smem + SM_B + 512);
    int*   mi1 = (int*)  (smem + SM_B + 1024);
    if (wn == 0 && (lane & 3) == 0) {
        #pragma unroll
        for (int m = 0; m < 4; m++) {
            int rl = wm * 32 + q + m * 8;
            md1[rl] = d1[m]; md2[rl] = d2[m]; mi1[rl] = i1[m];
        }
    }
    __syncthreads();
    if (wn == 1 && (lane & 3) == 0) {
        #pragma unroll
        for (int m = 0; m < 4; m++) {
            int rl  = wm * 32 + q + m * 8;
            int row = mtile * 128 + rl;
            float oa = md1[rl], oa2 = md2[rl];
            int   ia = mi1[rl];
            float D1, D2; int I1;
            if (d1[m] < oa) { D1 = d1[m]; I1 = i1[m]; D2 = fminf(oa, d2[m]); }
            else            { D1 = oa;    I1 = ia;    D2 = fminf(d1[m], oa2); }
            g_idx[row] = I1;
            float thr = a32r[m] * 9.536743e-7f;   // 8 * 2^-23 * a32
            if (!((D2 - D1) > thr)) {
                int pos = atomicAdd(&g_nflag, 1);
                if (pos < N_ROWS) g_flagged[pos] = row;
            }
        }
    }
}

// ---------------------------------------------------------------------------
// Exact re-rank of flagged rows over the 16 pooled candidates.
// ---------------------------------------------------------------------------
__global__ __launch_bounds__(256)
void vq_exact(const float* __restrict__ xall, const float* __restrict__ emb) {
    int nf = g_nflag;
    if (nf > N_ROWS) nf = N_ROWS;
    int lane  = threadIdx.x & 31;
    int warp  = (blockIdx.x * blockDim.x + threadIdx.x) >> 5;
    int nwarp = (gridDim.x * blockDim.x) >> 5;

    for (int f = warp; f < nf; f += nwarp) {
        int row = g_flagged[f];
        float bestd = 3.4e38f;
        int   besti = 0x7fffffff;
        if (lane < 16) {
            float4 qq = g_part[(size_t)row * 8 + (lane >> 1)];
            int k = (lane & 1) ? __float_as_int(qq.w) : __float_as_int(qq.z);
            const float* x = xall + (size_t)row * DIM;
            const float* e = emb  + (size_t)k * DIM;
            double ad = 0.0;
            float s = 0.f, c = 0.f;
            #pragma unroll
            for (int j = 0; j < DIM; j++) {
                float xv = __ldg(x + j), ev = __ldg(e + j);
                ad += (double)xv * (double)xv;
                float pr = __fmul_rn(xv, ev);
                float pe = fmaf(xv, ev, -pr);
                float t  = __fadd_rn(s, pr);
                float z  = __fadd_rn(t, -s);
                float se = __fadd_rn(__fadd_rn(s, -__fadd_rn(t, -z)),
                                     __fadd_rn(pr, -z));
                s = t;
                c = __fadd_rn(c, __fadd_rn(pe, se));
            }
            float a32 = (float)ad;
            float m  = __fadd_rn(s, c);
            float t2 = __fadd_rn(a32, g_b32[k]);
            bestd = __fadd_rn(t2, -__fmul_rn(2.0f, m));
            besti = k;
        }
        #pragma unroll
        for (int off = 8; off > 0; off >>= 1) {
            float od = __shfl_down_sync(0xffffffffu, bestd, off);
            int   oi = __shfl_down_sync(0xffffffffu, besti, off);
            if (od < bestd || (od == bestd && oi < besti)) { bestd = od; besti = oi; }
        }
        if (lane == 0) g_idx[row] = besti;
    }
}

// ---------------------------------------------------------------------------
// Fused outputs: warp per row. st/qorig + full one-hot row write + histogram.
// Streaming stores (cs) — outputs are never re-read.
// ---------------------------------------------------------------------------
__global__ __launch_bounds__(256)
void vq_outputs(const float* __restrict__ xall, const float* __restrict__ emb,
                float* __restrict__ out) {
    int warp = threadIdx.x >> 5;
    int lane = threadIdx.x & 31;
    int row  = blockIdx.x * 8 + warp;
    int idx  = g_idx[row];

    if (lane == 0) atomicAdd(&g_counts[idx], 1);

    float2 q  = ((const float2*)(emb  + (size_t)idx * DIM))[lane];
    float2 xv = ((const float2*)(xall + (size_t)row * DIM))[lane];
    float2 st;
    st.x = __fadd_rn(xv.x, __fadd_rn(q.x, -xv.x));
    st.y = __fadd_rn(xv.y, __fadd_rn(q.y, -xv.y));
    __stcs((float2*)(out + OFF_QST   + (size_t)row * DIM) + lane, st);
    __stcs((float2*)(out + OFF_QORIG + (size_t)row * DIM) + lane, q);

    // one-hot row: head (els 0-2), float4 body (els 3..1022), tail (el 1023)
    float* er = out + OFF_ENC + (size_t)row * K_EMB;
    if (lane < 3) __stcs(er + lane, (lane == idx) ? 1.0f : 0.0f);
    if (lane == 3) __stcs(er + 1023, (idx == 1023) ? 1.0f : 0.0f);
    float4* body = (float4*)(er + 3);   // 16B-aligned
    #pragma unroll
    for (int u = 0; u < 8; u++) {
        int i = u * 32 + lane;
        if (i < 255) {
            int k0 = 3 + i * 4;
            float4 v;
            v.x = (k0     == idx) ? 1.0f : 0.0f;
            v.y = (k0 + 1 == idx) ? 1.0f : 0.0f;
            v.z = (k0 + 2 == idx) ? 1.0f : 0.0f;
            v.w = (k0 + 3 == idx) ? 1.0f : 0.0f;
            __stcs(body + i, v);
        }
    }
}

// ---------------------------------------------------------------------------
__global__ void vq_perplexity(float* __restrict__ out) {
    __shared__ double s[256];
    double local = 0.0;
    for (int k = threadIdx.x; k < K_EMB; k += 256) {
        double p = (double)g_counts[k] * (1.0 / 131072.0);
        local += p * log(p + 1e-10);
    }
    s[threadIdx.x] = local;
    __syncthreads();
    for (int off = 128; off > 0; off >>= 1) {
        if (threadIdx.x < off) s[threadIdx.x] += s[threadIdx.x + off];
        __syncthreads();
    }
    if (threadIdx.x == 0) out[OFF_PERP] = (float)exp(-s[0]);
}

// ---------------------------------------------------------------------------
extern "C" void kernel_launch(void* const* d_in, const int* in_sizes, int n_in,
                              void* d_out, int out_size) {
    const float* x   = (const float*)d_in[0];
    const float* emb = (const float*)d_in[1];
    float* out = (float*)d_out;

    cudaFuncSetAttribute(vq_mma, cudaFuncAttributeMaxDynamicSharedMemorySize, SM_TOTAL);

    vq_convert_emb<<<128, 256>>>(emb);
    vq_mma<<<1024, 256, SM_TOTAL>>>(x);
    vq_exact<<<256, 256>>>(x, emb);
    vq_outputs<<<N_ROWS / 8, 256>>>(x, emb, out);
    vq_perplexity<<<1, 256>>>(out);
}

// round 8
// speedup vs baseline: 5.2036x; 1.1221x over previous
#include <cuda_runtime.h>
#include <cuda_bf16.h>
#include <math.h>

#define N_ROWS 131072
#define DIM 64
#define K_EMB 1024

// Output layout (tuple order: quantized_st, quantized_original, perplexity, encodings)
#define OFF_QST   0
#define OFF_QORIG 8388608
#define OFF_PERP  16777216
#define OFF_ENC   16777217
#define ENC_COUNT ((size_t)N_ROWS * K_EMB)

__device__ int   g_idx[N_ROWS];
__device__ float g_b32[K_EMB];
__device__ int   g_counts[K_EMB];
__device__ int   g_flagged[N_ROWS];
__device__ int   g_nflag;
// embeddings, bf16-split, pre-swizzled: per code row 16 chunks of 16B:
// chunks 0-7 = eh, chunks 8-15 = el. (The duplicated eh block of the K=192
// concat is realized by address aliasing in the MMA k-loop, not by storage.)
__device__ uint4 g_e_swz[16384];           // 1024 rows x 256 B
// candidate pool: per row 8 float4 = 16 (d, idx) candidates
__device__ float4 g_part[(size_t)N_ROWS * 8];

// ---------------------------------------------------------------------------
// helpers
// ---------------------------------------------------------------------------
__device__ __forceinline__ unsigned smem_u32(const void* p) {
    unsigned a;
    asm("{ .reg .u64 t; cvta.to.shared.u64 t, %1; cvt.u32.u64 %0, t; }"
        : "=r"(a) : "l"(p));
    return a;
}
__device__ __forceinline__ void ldsm4(unsigned* r, unsigned addr) {
    asm volatile("ldmatrix.sync.aligned.m8n8.x4.shared.b16 {%0,%1,%2,%3}, [%4];"
                 : "=r"(r[0]), "=r"(r[1]), "=r"(r[2]), "=r"(r[3]) : "r"(addr));
}
__device__ __forceinline__ void mma_bf16(float* d, const unsigned* a, const unsigned* b) {
    asm volatile(
        "mma.sync.aligned.m16n8k16.row.col.f32.bf16.bf16.f32 "
        "{%0,%1,%2,%3}, {%4,%5,%6,%7}, {%8,%9}, {%0,%1,%2,%3};"
        : "+f"(d[0]), "+f"(d[1]), "+f"(d[2]), "+f"(d[3])
        : "r"(a[0]), "r"(a[1]), "r"(a[2]), "r"(a[3]), "r"(b[0]), "r"(b[1]));
}
__device__ __forceinline__ void cp_async16(unsigned dst, const void* src) {
    asm volatile("cp.async.cg.shared.global [%0], [%1], 16;"
                 :: "r"(dst), "l"(src));
}
#define CP_COMMIT() asm volatile("cp.async.commit_group;" ::: "memory")
#define CP_WAIT0()  asm volatile("cp.async.wait_group 0;" ::: "memory")

// pack two floats' bf16-high parts into one u32; also produce residual pack
__device__ __forceinline__ void split2(float x, float y, unsigned& hp, unsigned& lp) {
    __nv_bfloat16 hx = __float2bfloat16_rn(x);
    __nv_bfloat16 hy = __float2bfloat16_rn(y);
    __nv_bfloat16 lx = __float2bfloat16_rn(__fadd_rn(x, -__bfloat162float(hx)));
    __nv_bfloat16 ly = __float2bfloat16_rn(__fadd_rn(y, -__bfloat162float(hy)));
    hp = ((unsigned)__bfloat16_as_ushort(hy) << 16) | __bfloat16_as_ushort(hx);
    lp = ((unsigned)__bfloat16_as_ushort(ly) << 16) | __bfloat16_as_ushort(lx);
}

// swizzled byte offset within a 128-row x 16-chunk tile (chunk = 16B, 256B/row)
#define SWZ16(r, c) ((r) * 256 + ((((c) & 8) | (((c) & 7) ^ ((r) & 7))) << 4))

// ---------------------------------------------------------------------------
// Convert embeddings -> pre-swizzled bf16-split tiles [eh | el]; b32;
// zero counts/nflag. One warp per code row.
// ---------------------------------------------------------------------------
__global__ void vq_convert_emb(const float* __restrict__ emb) {
    int lane = threadIdx.x & 31;
    int row  = (blockIdx.x * blockDim.x + threadIdx.x) >> 5;
    if (blockIdx.x == 0 && threadIdx.x == 0) g_nflag = 0;
    if (row >= K_EMB) return;

    float2 v = ((const float2*)(emb + (size_t)row * DIM))[lane];
    unsigned hp, lp;
    split2(v.x, v.y, hp, lp);
    int tile = row >> 7, r = row & 127;
    unsigned char* tb = (unsigned char*)g_e_swz + tile * 32768;
    int c   = lane >> 2;
    int pos = (lane & 3) * 4;
    *(unsigned*)(tb + SWZ16(r, c)     + pos) = hp;   // eh
    *(unsigned*)(tb + SWZ16(r, 8 + c) + pos) = lp;   // el

    double s = (double)v.x * v.x + (double)v.y * v.y;
    #pragma unroll
    for (int off = 16; off > 0; off >>= 1)
        s += __shfl_down_sync(0xffffffffu, s, off);
    if (lane == 0) { g_b32[row] = (float)s; g_counts[row] = 0; }
}

// ---------------------------------------------------------------------------
// Fused convert-x + HMMA distance + top-2 + combine + flag.
// CTA = 128 rows; warps 4x2: wm (32 rows) x wn (64 codes). B double-buffered
// via cp.async; A/B store only unique blocks (xh|xl, eh|el) and the k-loop
// aliases addresses to realize [xh,xl,xh].[eh,eh,el].
// SMEM: bs[1024]f @0, a32s @4096, A @5120 (32KB), B0 @37888, B1 @70656.
// ---------------------------------------------------------------------------
#define SM_A  5120
#define SM_B0 37888
#define SM_B1 70656
#define SM_TOTAL 103424

__global__ __launch_bounds__(256, 2) void vq_mma(const float* __restrict__ xall) {
    extern __shared__ char smem[];
    float* bs   = (float*)smem;
    float* a32s = (float*)(smem + 4096);
    unsigned sbase = smem_u32(smem);
    int tid  = threadIdx.x;
    int wid  = tid >> 5;
    int lane = tid & 31;
    int l7   = lane & 7;
    int wm   = wid & 3;       // 4 row-groups of 32
    int wn   = wid >> 2;      // 2 code-halves of 64
    int mtile = blockIdx.x;

    // prefetch ntile 0 into B0
    {
        const uint4* src = g_e_swz;
        #pragma unroll
        for (int u = 0; u < 8; u++) {
            int i = u * 256 + tid;
            cp_async16(sbase + SM_B0 + i * 16, src + i);
        }
        CP_COMMIT();
    }

    // Phase 0: bs fill + A convert-fill [xh | xl] + a32
    for (int i = tid; i < K_EMB; i += 256) bs[i] = g_b32[i];
    {
        int r = tid >> 1, h = tid & 1;
        const float4* xr = (const float4*)(xall + ((size_t)(mtile * 128 + r)) * DIM + h * 32);
        double ss = 0.0;
        #pragma unroll
        for (int j = 0; j < 4; j++) {
            float4 f0 = xr[2 * j];
            float4 f1 = xr[2 * j + 1];
            ss += (double)f0.x * f0.x + (double)f0.y * f0.y
                + (double)f0.z * f0.z + (double)f0.w * f0.w
                + (double)f1.x * f1.x + (double)f1.y * f1.y
                + (double)f1.z * f1.z + (double)f1.w * f1.w;
            uint4 hp4, lp4;
            split2(f0.x, f0.y, hp4.x, lp4.x);
            split2(f0.z, f0.w, hp4.y, lp4.y);
            split2(f1.x, f1.y, hp4.z, lp4.z);
            split2(f1.z, f1.w, hp4.w, lp4.w);
            int c = h * 4 + j;
            *(uint4*)(smem + SM_A + SWZ16(r, c))     = hp4;  // xh
            *(uint4*)(smem + SM_A + SWZ16(r, 8 + c)) = lp4;  // xl
        }
        ss += __shfl_xor_sync(0xffffffffu, ss, 1);
        if (h == 0) a32s[r] = (float)ss;
    }

    // ldmatrix base addresses
    int a_sub = ((lane >> 3) & 1) * 8 + l7;
    int a_ch  = (lane >> 4) & 1;
    unsigned abase0 = sbase + SM_A + (wm * 32 + a_sub) * 256;
    unsigned abase1 = abase0 + 16 * 256;
    int b_sub = ((lane >> 4) & 1) * 8 + l7;
    int b_ch  = (lane >> 3) & 1;
    unsigned brow = (wn * 64 + b_sub) * 256;

    int q    = lane >> 2;       // row-within-8 owner
    int cpos = (lane & 3) * 2;  // col pair within n8

    CP_WAIT0();
    __syncthreads();

    float a32r[4];
    #pragma unroll
    for (int m = 0; m < 4; m++) a32r[m] = a32s[wm * 32 + q + m * 8];

    float d1[4], d2[4];
    int   i1[4], i2[4];
    #pragma unroll
    for (int m = 0; m < 4; m++) { d1[m] = 3.4e38f; d2[m] = 3.4e38f; i1[m] = 0; i2[m] = 0; }

    for (int nt = 0; nt < 8; nt++) {
        unsigned bcur = sbase + ((nt & 1) ? SM_B1 : SM_B0);
        if (nt < 7) {
            unsigned bnext = sbase + ((nt & 1) ? SM_B0 : SM_B1);
            const uint4* src = g_e_swz + (nt + 1) * 2048;
            #pragma unroll
            for (int u = 0; u < 8; u++) {
                int i = u * 256 + tid;
                cp_async16(bnext + i * 16, src + i);
            }
            CP_COMMIT();
        }

        unsigned bbase = bcur + brow;

        #pragma unroll
        for (int half = 0; half < 2; half++) {
            float acc[2][4][4];
            #pragma unroll
            for (int t = 0; t < 2; t++)
                #pragma unroll
                for (int j = 0; j < 4; j++) {
                    acc[t][j][0] = 0.f; acc[t][j][1] = 0.f;
                    acc[t][j][2] = 0.f; acc[t][j][3] = 0.f;
                }

            #pragma unroll
            for (int ks = 0; ks < 12; ks++) {
                // A block alias: ks 0-3 -> xh, 4-7 -> xl, 8-11 -> xh
                int pa = (ks < 8) ? ks : (ks - 8);
                int ca = 2 * pa + a_ch;
                unsigned aoff = (((ca & 8) | ((ca & 7) ^ l7)) << 4);
                unsigned af0[4], af1[4];
                ldsm4(af0, abase0 + aoff);
                ldsm4(af1, abase1 + aoff);
                // B block alias: ks 0-3 -> eh, 4-7 -> eh, 8-11 -> el
                int pb = (ks < 4) ? ks : (ks - 4);
                int cb = 2 * pb + b_ch;
                unsigned boff = (((cb & 8) | ((cb & 7) ^ l7)) << 4);
                #pragma unroll
                for (int g = 0; g < 2; g++) {
                    int cg = half * 2 + g;
                    unsigned bf[4];
                    ldsm4(bf, bbase + cg * (16 * 256) + boff);
                    mma_bf16(acc[0][2 * g],     af0, bf);
                    mma_bf16(acc[0][2 * g + 1], af0, bf + 2);
                    mma_bf16(acc[1][2 * g],     af1, bf);
                    mma_bf16(acc[1][2 * g + 1], af1, bf + 2);
                }
            }

            // epilogue: d = fl(fl(a32+b) - 2m); branchy top-2 (updates rare)
            int colbase = nt * 128 + wn * 64 + half * 32;
            #pragma unroll
            for (int j = 0; j < 4; j++) {
                float2 bv = *(float2*)&bs[colbase + j * 8 + cpos];
                int k0 = colbase + j * 8 + cpos;
                #pragma unroll
                for (int t = 0; t < 2; t++) {
                    #pragma unroll
                    for (int rr = 0; rr < 2; rr++) {
                        int m = t * 2 + rr;
                        float ta = a32r[m];
                        float v0 = fmaf(acc[t][j][2 * rr],     -2.0f, __fadd_rn(ta, bv.x));
                        float v1 = fmaf(acc[t][j][2 * rr + 1], -2.0f, __fadd_rn(ta, bv.y));
                        if (v0 < d2[m]) {
                            if (v0 < d1[m]) { d2[m] = d1[m]; i2[m] = i1[m];
                                              d1[m] = v0;    i1[m] = k0; }
                            else            { d2[m] = v0;    i2[m] = k0; }
                        }
                        if (v1 < d2[m]) {
                            if (v1 < d1[m]) { d2[m] = d1[m]; i2[m] = i1[m];
                                              d1[m] = v1;    i1[m] = k0 + 1; }
                            else            { d2[m] = v1;    i2[m] = k0 + 1; }
                        }
                    }
                }
            }
        }
        CP_WAIT0();
        __syncthreads();
    }

    // candidate pool: per lane, per row: (d1,d2,i1,i2)
    #pragma unroll
    for (int m = 0; m < 4; m++) {
        int row = mtile * 128 + wm * 32 + q + m * 8;
        g_part[(size_t)row * 8 + wn * 4 + (lane & 3)] =
            make_float4(d1[m], d2[m], __int_as_float(i1[m]), __int_as_float(i2[m]));
    }

    // quad merge (lanes sharing a row); lowest-index tie-break
    #pragma unroll
    for (int off = 1; off <= 2; off <<= 1) {
        #pragma unroll
        for (int m = 0; m < 4; m++) {
            float od1 = __shfl_xor_sync(0xffffffffu, d1[m], off);
            int   oi1 = __shfl_xor_sync(0xffffffffu, i1[m], off);
            float od2 = __shfl_xor_sync(0xffffffffu, d2[m], off);
            int   oi2 = __shfl_xor_sync(0xffffffffu, i2[m], off);
            if (od1 < d1[m] || (od1 == d1[m] && oi1 < i1[m])) {
                float t = d1[m]; int ti = i1[m];
                d1[m] = od1; i1[m] = oi1;
                if (od2 < t || (od2 == t && oi2 < ti)) { d2[m] = od2; i2[m] = oi2; }
                else                                   { d2[m] = t;   i2[m] = ti; }
            } else if (od1 < d2[m] || (od1 == d2[m] && oi1 < i2[m])) {
                d2[m] = od1; i2[m] = oi1;
            }
        }
    }

    // cross-half merge via smem (reuse B0 region)
    __syncthreads();
    float* md1 = (float*)(smem + SM_B0);
    float* md2 = (float*)(smem + SM_B0 + 512);
    int*   mi1 = (int*)  (smem + SM_B0 + 1024);
    if (wn == 0 && (lane & 3) == 0) {
        #pragma unroll
        for (int m = 0; m < 4; m++) {
            int rl = wm * 32 + q + m * 8;
            md1[rl] = d1[m]; md2[rl] = d2[m]; mi1[rl] = i1[m];
        }
    }
    __syncthreads();
    if (wn == 1 && (lane & 3) == 0) {
        #pragma unroll
        for (int m = 0; m < 4; m++) {
            int rl  = wm * 32 + q + m * 8;
            int row = mtile * 128 + rl;
            float oa = md1[rl], oa2 = md2[rl];
            int   ia = mi1[rl];
            float D1, D2; int I1;
            if (d1[m] < oa) { D1 = d1[m]; I1 = i1[m]; D2 = fminf(oa, d2[m]); }
            else            { D1 = oa;    I1 = ia;    D2 = fminf(d1[m], oa2); }
            g_idx[row] = I1;
            float thr = a32r[m] * 9.536743e-7f;   // 8 * 2^-23 * a32
            if (!((D2 - D1) > thr)) {
                int pos = atomicAdd(&g_nflag, 1);
                if (pos < N_ROWS) g_flagged[pos] = row;
            }
        }
    }
}

// ---------------------------------------------------------------------------
// Exact re-rank of flagged rows over the 16 pooled candidates.
// ---------------------------------------------------------------------------
__global__ __launch_bounds__(256)
void vq_exact(const float* __restrict__ xall, const float* __restrict__ emb) {
    int nf = g_nflag;
    if (nf > N_ROWS) nf = N_ROWS;
    int lane  = threadIdx.x & 31;
    int warp  = (blockIdx.x * blockDim.x + threadIdx.x) >> 5;
    int nwarp = (gridDim.x * blockDim.x) >> 5;

    for (int f = warp; f < nf; f += nwarp) {
        int row = g_flagged[f];
        float bestd = 3.4e38f;
        int   besti = 0x7fffffff;
        if (lane < 16) {
            float4 qq = g_part[(size_t)row * 8 + (lane >> 1)];
            int k = (lane & 1) ? __float_as_int(qq.w) : __float_as_int(qq.z);
            const float* x = xall + (size_t)row * DIM;
            const float* e = emb  + (size_t)k * DIM;
            double ad = 0.0;
            float s = 0.f, c = 0.f;
            #pragma unroll
            for (int j = 0; j < DIM; j++) {
                float xv = __ldg(x + j), ev = __ldg(e + j);
                ad += (double)xv * (double)xv;
                float pr = __fmul_rn(xv, ev);
                float pe = fmaf(xv, ev, -pr);
                float t  = __fadd_rn(s, pr);
                float z  = __fadd_rn(t, -s);
                float se = __fadd_rn(__fadd_rn(s, -__fadd_rn(t, -z)),
                                     __fadd_rn(pr, -z));
                s = t;
                c = __fadd_rn(c, __fadd_rn(pe, se));
            }
            float a32 = (float)ad;
            float m  = __fadd_rn(s, c);
            float t2 = __fadd_rn(a32, g_b32[k]);
            bestd = __fadd_rn(t2, -__fmul_rn(2.0f, m));
            besti = k;
        }
        #pragma unroll
        for (int off = 8; off > 0; off >>= 1) {
            float od = __shfl_down_sync(0xffffffffu, bestd, off);
            int   oi = __shfl_down_sync(0xffffffffu, besti, off);
            if (od < bestd || (od == bestd && oi < besti)) { bestd = od; besti = oi; }
        }
        if (lane == 0) g_idx[row] = besti;
    }
}

// ---------------------------------------------------------------------------
// Fused outputs: warp per row. st/qorig + full one-hot row write + histogram.
// Streaming stores (cs) — outputs are never re-read.
// ---------------------------------------------------------------------------
__global__ __launch_bounds__(256)
void vq_outputs(const float* __restrict__ xall, const float* __restrict__ emb,
                float* __restrict__ out) {
    int warp = threadIdx.x >> 5;
    int lane = threadIdx.x & 31;
    int row  = blockIdx.x * 8 + warp;
    int idx  = g_idx[row];

    if (lane == 0) atomicAdd(&g_counts[idx], 1);

    float2 q  = ((const float2*)(emb  + (size_t)idx * DIM))[lane];
    float2 xv = ((const float2*)(xall + (size_t)row * DIM))[lane];
    float2 st;
    st.x = __fadd_rn(xv.x, __fadd_rn(q.x, -xv.x));
    st.y = __fadd_rn(xv.y, __fadd_rn(q.y, -xv.y));
    __stcs((float2*)(out + OFF_QST   + (size_t)row * DIM) + lane, st);
    __stcs((float2*)(out + OFF_QORIG + (size_t)row * DIM) + lane, q);

    // one-hot row: head (els 0-2), float4 body (els 3..1022), tail (el 1023)
    float* er = out + OFF_ENC + (size_t)row * K_EMB;
    if (lane < 3) __stcs(er + lane, (lane == idx) ? 1.0f : 0.0f);
    if (lane == 3) __stcs(er + 1023, (idx == 1023) ? 1.0f : 0.0f);
    float4* body = (float4*)(er + 3);   // 16B-aligned
    #pragma unroll
    for (int u = 0; u < 8; u++) {
        int i = u * 32 + lane;
        if (i < 255) {
            int k0 = 3 + i * 4;
            float4 v;
            v.x = (k0     == idx) ? 1.0f : 0.0f;
            v.y = (k0 + 1 == idx) ? 1.0f : 0.0f;
            v.z = (k0 + 2 == idx) ? 1.0f : 0.0f;
            v.w = (k0 + 3 == idx) ? 1.0f : 0.0f;
            __stcs(body + i, v);
        }
    }
}

// ---------------------------------------------------------------------------
__global__ void vq_perplexity(float* __restrict__ out) {
    __shared__ double s[256];
    double local = 0.0;
    for (int k = threadIdx.x; k < K_EMB; k += 256) {
        double p = (double)g_counts[k] * (1.0 / 131072.0);
        local += p * log(p + 1e-10);
    }
    s[threadIdx.x] = local;
    __syncthreads();
    for (int off = 128; off > 0; off >>= 1) {
        if (threadIdx.x < off) s[threadIdx.x] += s[threadIdx.x + off];
        __syncthreads();
    }
    if (threadIdx.x == 0) out[OFF_PERP] = (float)exp(-s[0]);
}

// ---------------------------------------------------------------------------
extern "C" void kernel_launch(void* const* d_in, const int* in_sizes, int n_in,
                              void* d_out, int out_size) {
    const float* x   = (const float*)d_in[0];
    const float* emb = (const float*)d_in[1];
    float* out = (float*)d_out;

    cudaFuncSetAttribute(vq_mma, cudaFuncAttributeMaxDynamicSharedMemorySize, SM_TOTAL);

    vq_convert_emb<<<128, 256>>>(emb);
    vq_mma<<<1024, 256, SM_TOTAL>>>(x);
    vq_exact<<<256, 256>>>(x, emb);
    vq_outputs<<<N_ROWS / 8, 256>>>(x, emb, out);
    vq_perplexity<<<1, 256>>>(out);
}